// round 2
// baseline (speedup 1.0000x reference)
#include <cuda_runtime.h>

#define VN 48
#define VNN (48*48)
#define VNNN (48*48*48)
#define NB 8
#define NCH 32
#define NHID 64
#define SP_EPS 1e-5f
#define TILE 8
#define TPD 6   // tiles per dim = 48/8

typedef unsigned long long u64;

__device__ float g_actv[(size_t)NB * NHID * VNNN];
__device__ float g_mu[NB * NCH];
__device__ float g_rsig[NB * NCH];

__device__ __forceinline__ u64 pack2(float lo, float hi) {
    u64 r; asm("mov.b64 %0, {%1, %2};" : "=l"(r) : "f"(lo), "f"(hi)); return r;
}
__device__ __forceinline__ float2 unpack2(u64 v) {
    float2 f; asm("mov.b64 {%0, %1}, %2;" : "=f"(f.x), "=f"(f.y) : "l"(v)); return f;
}
__device__ __forceinline__ void ffma2(u64& d, u64 a, u64 b) {
    asm("fma.rn.f32x2 %0, %1, %2, %0;" : "+l"(d) : "l"(a), "l"(b));
}

// ---------------------------------------------------------------------------
// Kernel A: per-(b,c) mean / rsqrt(var+eps) over 48^3
// ---------------------------------------------------------------------------
__global__ void stats_kernel(const float* __restrict__ x) {
    int bc = blockIdx.x;
    const float4* xp = reinterpret_cast<const float4*>(x + (size_t)bc * VNNN);
    float s = 0.f, ss = 0.f;
    for (int i = threadIdx.x; i < VNNN / 4; i += blockDim.x) {
        float4 v = xp[i];
        s  += v.x + v.y + v.z + v.w;
        ss += v.x * v.x + v.y * v.y + v.z * v.z + v.w * v.w;
    }
    __shared__ float sh_s[8], sh_ss[8];
    #pragma unroll
    for (int o = 16; o; o >>= 1) {
        s  += __shfl_down_sync(0xffffffffu, s, o);
        ss += __shfl_down_sync(0xffffffffu, ss, o);
    }
    int w = threadIdx.x >> 5, l = threadIdx.x & 31;
    if (l == 0) { sh_s[w] = s; sh_ss[w] = ss; }
    __syncthreads();
    if (w == 0) {
        int nw = blockDim.x >> 5;
        s  = (l < nw) ? sh_s[l]  : 0.f;
        ss = (l < nw) ? sh_ss[l] : 0.f;
        #pragma unroll
        for (int o = 4; o; o >>= 1) {
            s  += __shfl_down_sync(0xffffffffu, s, o);
            ss += __shfl_down_sync(0xffffffffu, ss, o);
        }
        if (l == 0) {
            float mu  = s / (float)VNNN;
            float var = ss / (float)VNNN - mu * mu;
            g_mu[bc]   = mu;
            g_rsig[bc] = rsqrtf(var + SP_EPS);
        }
    }
}

// ---------------------------------------------------------------------------
// Kernel B: actv = relu(conv3d(x, Wshared[y]) + bshared[y])   32 -> 64 ch
// FFMA2 (packed f32x2): thread = x-row of 8 (4 pairs) x 8 oc
// grid: (216 tiles, 4 oc-blocks of 16, 8 batch); 128 threads
// ---------------------------------------------------------------------------
#define OC1 16
__global__ __launch_bounds__(128)
void conv1_kernel(const float* __restrict__ x, const float* __restrict__ Ws,
                  const float* __restrict__ bs, const int* __restrict__ ycls) {
    __shared__ float s_in[8 * 1000];          // 8 ic, 10x10x10 halo tile
    __shared__ float s_w[8 * 27 * OC1 * 2];   // [ic][k][oc][dup2]

    int t  = blockIdx.x;
    int tx = t % TPD, ty = (t / TPD) % TPD, tz = t / (TPD * TPD);
    int ocb = blockIdx.y;
    int b   = blockIdx.z;
    int cls = ycls[b];
    int tid = threadIdx.x;
    int row = tid & 63;
    int ly = row & 7, lz = row >> 3;
    int och = tid >> 6;                       // which 8 of the 16 oc
    int x0 = tx * TILE, y0 = ty * TILE, z0 = tz * TILE;

    u64 acc[8][4];
    #pragma unroll
    for (int o = 0; o < 8; o++)
        #pragma unroll
        for (int m = 0; m < 4; m++) acc[o][m] = 0ULL;

    const float* Wbase = Ws + ((size_t)cls * NHID + (size_t)ocb * OC1) * (NCH * 27);

    for (int c0 = 0; c0 < NCH; c0 += 8) {
        const float* xb = x + ((size_t)b * NCH + c0) * VNNN;
        for (int i = tid; i < 8000; i += 128) {
            int ic = i / 1000; int r = i - ic * 1000;
            int zz = r / 100;  r -= zz * 100;
            int yy = r / 10;   int xx = r - yy * 10;
            int gz = z0 + zz - 1, gy = y0 + yy - 1, gx = x0 + xx - 1;
            float v = 0.f;
            if ((unsigned)gz < VN && (unsigned)gy < VN && (unsigned)gx < VN)
                v = xb[(size_t)ic * VNNN + gz * VNN + gy * VN + gx];
            s_in[i] = v;
        }
        for (int i = tid; i < 8 * 27 * OC1; i += 128) {
            int oc = i % OC1;
            int r  = i / OC1;
            int k  = r % 27;
            int ic = r / 27;
            float w = Wbase[(size_t)oc * (NCH * 27) + (size_t)(c0 + ic) * 27 + k];
            s_w[i * 2] = w; s_w[i * 2 + 1] = w;
        }
        __syncthreads();

        #pragma unroll 1
        for (int ic = 0; ic < 8; ++ic) {
            #pragma unroll 1
            for (int kd = 0; kd < 3; ++kd) {
                #pragma unroll 1
                for (int kh = 0; kh < 3; ++kh) {
                    const float* rp = &s_in[ic * 1000 + (lz + kd) * 100 + (ly + kh) * 10];
                    float2 r0 = *(const float2*)(rp + 0);
                    float2 r1 = *(const float2*)(rp + 2);
                    float2 r2 = *(const float2*)(rp + 4);
                    float2 r3 = *(const float2*)(rp + 6);
                    float2 r4 = *(const float2*)(rp + 8);
                    u64 A[3][4];
                    A[0][0] = pack2(r0.x, r0.y); A[0][1] = pack2(r1.x, r1.y);
                    A[0][2] = pack2(r2.x, r2.y); A[0][3] = pack2(r3.x, r3.y);
                    A[1][0] = pack2(r0.y, r1.x); A[1][1] = pack2(r1.y, r2.x);
                    A[1][2] = pack2(r2.y, r3.x); A[1][3] = pack2(r3.y, r4.x);
                    A[2][0] = pack2(r1.x, r1.y); A[2][1] = pack2(r2.x, r2.y);
                    A[2][2] = pack2(r3.x, r3.y); A[2][3] = pack2(r4.x, r4.y);
                    int kb = (kd * 3 + kh) * 3;
                    const u64* wp = (const u64*)s_w + (size_t)(ic * 27 + kb) * OC1 + och * 8;
                    #pragma unroll
                    for (int kw = 0; kw < 3; ++kw) {
                        const u64* wk = wp + kw * OC1;
                        #pragma unroll
                        for (int o = 0; o < 8; ++o) {
                            u64 w = wk[o];
                            #pragma unroll
                            for (int m = 0; m < 4; ++m) ffma2(acc[o][m], A[kw][m], w);
                        }
                    }
                }
            }
        }
        __syncthreads();
    }

    int gy = y0 + ly, gz = z0 + lz;
    #pragma unroll
    for (int o = 0; o < 8; ++o) {
        int ocg = ocb * OC1 + och * 8 + o;
        float bias = bs[cls * NHID + ocg];
        float* outp = g_actv + ((size_t)b * NHID + ocg) * VNNN
                    + (size_t)gz * VNN + (size_t)gy * VN + x0;
        float2 p0 = unpack2(acc[o][0]), p1 = unpack2(acc[o][1]);
        float2 p2 = unpack2(acc[o][2]), p3 = unpack2(acc[o][3]);
        float4 v0, v1;
        v0.x = fmaxf(p0.x + bias, 0.f); v0.y = fmaxf(p0.y + bias, 0.f);
        v0.z = fmaxf(p1.x + bias, 0.f); v0.w = fmaxf(p1.y + bias, 0.f);
        v1.x = fmaxf(p2.x + bias, 0.f); v1.y = fmaxf(p2.y + bias, 0.f);
        v1.z = fmaxf(p3.x + bias, 0.f); v1.w = fmaxf(p3.y + bias, 0.f);
        ((float4*)outp)[0] = v0;
        ((float4*)outp)[1] = v1;
    }
}

// ---------------------------------------------------------------------------
// Kernel C: gamma/beta convs (64 -> 32) fused with InstanceNorm epilogue
// grid: (216 tiles, 4 oc-blocks of 8, 8 batch); 128 threads
// thread = x-row of 8 (4 pairs) x (4 gamma oc + 4 beta oc, same oc set)
// ---------------------------------------------------------------------------
#define OC2 8
__global__ __launch_bounds__(128)
void conv2_kernel(const float* __restrict__ x,
                  const float* __restrict__ Wg, const float* __restrict__ bg,
                  const float* __restrict__ Wb, const float* __restrict__ bb,
                  const int* __restrict__ ycls, float* __restrict__ out) {
    __shared__ float s_in[8 * 1000];
    __shared__ float s_wg[8 * 27 * OC2 * 2];
    __shared__ float s_wb[8 * 27 * OC2 * 2];

    int t  = blockIdx.x;
    int tx = t % TPD, ty = (t / TPD) % TPD, tz = t / (TPD * TPD);
    int ocb = blockIdx.y;
    int b   = blockIdx.z;
    int cls = ycls[b];
    int tid = threadIdx.x;
    int row = tid & 63;
    int ly = row & 7, lz = row >> 3;
    int och = tid >> 6;                       // which 4 of the 8 oc
    int x0 = tx * TILE, y0 = ty * TILE, z0 = tz * TILE;

    u64 accg[4][4], accb[4][4];
    #pragma unroll
    for (int o = 0; o < 4; o++)
        #pragma unroll
        for (int m = 0; m < 4; m++) { accg[o][m] = 0ULL; accb[o][m] = 0ULL; }

    const float* Wgb = Wg + ((size_t)cls * NCH + (size_t)ocb * OC2) * (NHID * 27);
    const float* Wbb = Wb + ((size_t)cls * NCH + (size_t)ocb * OC2) * (NHID * 27);

    for (int c0 = 0; c0 < NHID; c0 += 8) {
        const float* ab = g_actv + ((size_t)b * NHID + c0) * VNNN;
        for (int i = tid; i < 8000; i += 128) {
            int ic = i / 1000; int r = i - ic * 1000;
            int zz = r / 100;  r -= zz * 100;
            int yy = r / 10;   int xx = r - yy * 10;
            int gz = z0 + zz - 1, gy = y0 + yy - 1, gx = x0 + xx - 1;
            float v = 0.f;
            if ((unsigned)gz < VN && (unsigned)gy < VN && (unsigned)gx < VN)
                v = ab[(size_t)ic * VNNN + gz * VNN + gy * VN + gx];
            s_in[i] = v;
        }
        for (int i = tid; i < 8 * 27 * OC2; i += 128) {
            int oc = i % OC2;
            int r  = i / OC2;
            int k  = r % 27;
            int ic = r / 27;
            size_t goff = (size_t)oc * (NHID * 27) + (size_t)(c0 + ic) * 27 + k;
            float wg = Wgb[goff];
            float wb = Wbb[goff];
            s_wg[i * 2] = wg; s_wg[i * 2 + 1] = wg;
            s_wb[i * 2] = wb; s_wb[i * 2 + 1] = wb;
        }
        __syncthreads();

        #pragma unroll 1
        for (int ic = 0; ic < 8; ++ic) {
            #pragma unroll 1
            for (int kd = 0; kd < 3; ++kd) {
                #pragma unroll 1
                for (int kh = 0; kh < 3; ++kh) {
                    const float* rp = &s_in[ic * 1000 + (lz + kd) * 100 + (ly + kh) * 10];
                    float2 r0 = *(const float2*)(rp + 0);
                    float2 r1 = *(const float2*)(rp + 2);
                    float2 r2 = *(const float2*)(rp + 4);
                    float2 r3 = *(const float2*)(rp + 6);
                    float2 r4 = *(const float2*)(rp + 8);
                    u64 A[3][4];
                    A[0][0] = pack2(r0.x, r0.y); A[0][1] = pack2(r1.x, r1.y);
                    A[0][2] = pack2(r2.x, r2.y); A[0][3] = pack2(r3.x, r3.y);
                    A[1][0] = pack2(r0.y, r1.x); A[1][1] = pack2(r1.y, r2.x);
                    A[1][2] = pack2(r2.y, r3.x); A[1][3] = pack2(r3.y, r4.x);
                    A[2][0] = pack2(r1.x, r1.y); A[2][1] = pack2(r2.x, r2.y);
                    A[2][2] = pack2(r3.x, r3.y); A[2][3] = pack2(r4.x, r4.y);
                    int kb = (kd * 3 + kh) * 3;
                    const u64* wpg = (const u64*)s_wg + (size_t)(ic * 27 + kb) * OC2 + och * 4;
                    const u64* wpb = (const u64*)s_wb + (size_t)(ic * 27 + kb) * OC2 + och * 4;
                    #pragma unroll
                    for (int kw = 0; kw < 3; ++kw) {
                        const u64* wkg = wpg + kw * OC2;
                        const u64* wkb = wpb + kw * OC2;
                        #pragma unroll
                        for (int o = 0; o < 4; ++o) {
                            u64 wg = wkg[o];
                            u64 wb = wkb[o];
                            #pragma unroll
                            for (int m = 0; m < 4; ++m) {
                                ffma2(accg[o][m], A[kw][m], wg);
                                ffma2(accb[o][m], A[kw][m], wb);
                            }
                        }
                    }
                }
            }
        }
        __syncthreads();
    }

    int gy = y0 + ly, gz = z0 + lz;
    #pragma unroll
    for (int o = 0; o < 4; ++o) {
        int ocg = ocb * OC2 + och * 4 + o;
        float bgv = bg[cls * NCH + ocg];
        float bbv = bb[cls * NCH + ocg];
        float mu  = g_mu[b * NCH + ocg];
        float rs  = g_rsig[b * NCH + ocg];
        size_t base = ((size_t)b * NCH + ocg) * VNNN
                    + (size_t)gz * VNN + (size_t)gy * VN + x0;
        const float4* xp = (const float4*)(x + base);
        float4* op = (float4*)(out + base);
        float2 g0 = unpack2(accg[o][0]), g1 = unpack2(accg[o][1]);
        float2 g2 = unpack2(accg[o][2]), g3 = unpack2(accg[o][3]);
        float2 b0 = unpack2(accb[o][0]), b1 = unpack2(accb[o][1]);
        float2 b2 = unpack2(accb[o][2]), b3 = unpack2(accb[o][3]);
        float4 xv0 = xp[0], xv1 = xp[1];
        float4 r0, r1;
        r0.x = (xv0.x - mu) * rs * (1.f + g0.x + bgv) + (b0.x + bbv);
        r0.y = (xv0.y - mu) * rs * (1.f + g0.y + bgv) + (b0.y + bbv);
        r0.z = (xv0.z - mu) * rs * (1.f + g1.x + bgv) + (b1.x + bbv);
        r0.w = (xv0.w - mu) * rs * (1.f + g1.y + bgv) + (b1.y + bbv);
        r1.x = (xv1.x - mu) * rs * (1.f + g2.x + bgv) + (b2.x + bbv);
        r1.y = (xv1.y - mu) * rs * (1.f + g2.y + bgv) + (b2.y + bbv);
        r1.z = (xv1.z - mu) * rs * (1.f + g3.x + bgv) + (b3.x + bbv);
        r1.w = (xv1.w - mu) * rs * (1.f + g3.y + bgv) + (b3.y + bbv);
        op[0] = r0;
        op[1] = r1;
    }
}

// ---------------------------------------------------------------------------
extern "C" void kernel_launch(void* const* d_in, const int* in_sizes, int n_in,
                              void* d_out, int out_size) {
    const float* x       = (const float*)d_in[0];
    const int*   y       = (const int*)d_in[1];
    const float* Wshared = (const float*)d_in[2];
    const float* bshared = (const float*)d_in[3];
    const float* Wgamma  = (const float*)d_in[4];
    const float* bgamma  = (const float*)d_in[5];
    const float* Wbeta   = (const float*)d_in[6];
    const float* bbeta   = (const float*)d_in[7];
    float* out = (float*)d_out;

    stats_kernel<<<NB * NCH, 256>>>(x);

    dim3 grid1(TPD * TPD * TPD, NHID / OC1, NB);
    conv1_kernel<<<grid1, 128>>>(x, Wshared, bshared, y);

    dim3 grid2(TPD * TPD * TPD, NCH / OC2, NB);
    conv2_kernel<<<grid2, 128>>>(x, Wgamma, bgamma, Wbeta, bbeta, y, out);
}

// round 3
// speedup vs baseline: 1.0010x; 1.0010x over previous
#include <cuda_runtime.h>

#define VN 48
#define VNN (48*48)
#define VNNN (48*48*48)
#define NB 8
#define NCH 32
#define NHID 64
#define SP_EPS 1e-5f
#define TILE 8
#define TPD 6   // tiles per dim = 48/8

typedef unsigned long long u64;

__device__ float g_actv[(size_t)NB * NHID * VNNN];
__device__ float g_mu[NB * NCH];
__device__ float g_rsig[NB * NCH];

__device__ __forceinline__ u64 pack2(float lo, float hi) {
    u64 r; asm("mov.b64 %0, {%1, %2};" : "=l"(r) : "f"(lo), "f"(hi)); return r;
}
__device__ __forceinline__ float2 unpack2(u64 v) {
    float2 f; asm("mov.b64 {%0, %1}, %2;" : "=f"(f.x), "=f"(f.y) : "l"(v)); return f;
}
__device__ __forceinline__ void ffma2(u64& d, u64 a, u64 b) {
    asm("fma.rn.f32x2 %0, %1, %2, %0;" : "+l"(d) : "l"(a), "l"(b));
}

// ---------------------------------------------------------------------------
// Kernel A: per-(b,c) mean / rsqrt(var+eps) over 48^3
// ---------------------------------------------------------------------------
__global__ void stats_kernel(const float* __restrict__ x) {
    int bc = blockIdx.x;
    const float4* xp = reinterpret_cast<const float4*>(x + (size_t)bc * VNNN);
    float s = 0.f, ss = 0.f;
    for (int i = threadIdx.x; i < VNNN / 4; i += blockDim.x) {
        float4 v = xp[i];
        s  += v.x + v.y + v.z + v.w;
        ss += v.x * v.x + v.y * v.y + v.z * v.z + v.w * v.w;
    }
    __shared__ float sh_s[8], sh_ss[8];
    #pragma unroll
    for (int o = 16; o; o >>= 1) {
        s  += __shfl_down_sync(0xffffffffu, s, o);
        ss += __shfl_down_sync(0xffffffffu, ss, o);
    }
    int w = threadIdx.x >> 5, l = threadIdx.x & 31;
    if (l == 0) { sh_s[w] = s; sh_ss[w] = ss; }
    __syncthreads();
    if (w == 0) {
        int nw = blockDim.x >> 5;
        s  = (l < nw) ? sh_s[l]  : 0.f;
        ss = (l < nw) ? sh_ss[l] : 0.f;
        #pragma unroll
        for (int o = 4; o; o >>= 1) {
            s  += __shfl_down_sync(0xffffffffu, s, o);
            ss += __shfl_down_sync(0xffffffffu, ss, o);
        }
        if (l == 0) {
            float mu  = s / (float)VNNN;
            float var = ss / (float)VNNN - mu * mu;
            g_mu[bc]   = mu;
            g_rsig[bc] = rsqrtf(var + SP_EPS);
        }
    }
}

// ---------------------------------------------------------------------------
// Kernel B: actv = relu(conv3d(x, Wshared[y]) + bshared[y])   32 -> 64 ch
// FFMA2 (packed f32x2): thread = x-row of 8 (4 pairs) x 8 oc
// grid: (216 tiles, 4 oc-blocks of 16, 8 batch); 128 threads
// ---------------------------------------------------------------------------
#define OC1 16
__global__ __launch_bounds__(128)
void conv1_kernel(const float* __restrict__ x, const float* __restrict__ Ws,
                  const float* __restrict__ bs, const int* __restrict__ ycls) {
    __shared__ float s_in[8 * 1000];          // 8 ic, 10x10x10 halo tile
    __shared__ float s_w[8 * 27 * OC1 * 2];   // [ic][k][oc][dup2]

    int t  = blockIdx.x;
    int tx = t % TPD, ty = (t / TPD) % TPD, tz = t / (TPD * TPD);
    int ocb = blockIdx.y;
    int b   = blockIdx.z;
    int cls = ycls[b];
    int tid = threadIdx.x;
    int row = tid & 63;
    int ly = row & 7, lz = row >> 3;
    int och = tid >> 6;                       // which 8 of the 16 oc
    int x0 = tx * TILE, y0 = ty * TILE, z0 = tz * TILE;

    u64 acc[8][4];
    #pragma unroll
    for (int o = 0; o < 8; o++)
        #pragma unroll
        for (int m = 0; m < 4; m++) acc[o][m] = 0ULL;

    const float* Wbase = Ws + ((size_t)cls * NHID + (size_t)ocb * OC1) * (NCH * 27);

    for (int c0 = 0; c0 < NCH; c0 += 8) {
        const float* xb = x + ((size_t)b * NCH + c0) * VNNN;
        for (int i = tid; i < 8000; i += 128) {
            int ic = i / 1000; int r = i - ic * 1000;
            int zz = r / 100;  r -= zz * 100;
            int yy = r / 10;   int xx = r - yy * 10;
            int gz = z0 + zz - 1, gy = y0 + yy - 1, gx = x0 + xx - 1;
            float v = 0.f;
            if ((unsigned)gz < VN && (unsigned)gy < VN && (unsigned)gx < VN)
                v = xb[(size_t)ic * VNNN + gz * VNN + gy * VN + gx];
            s_in[i] = v;
        }
        for (int i = tid; i < 8 * 27 * OC1; i += 128) {
            int oc = i % OC1;
            int r  = i / OC1;
            int k  = r % 27;
            int ic = r / 27;
            float w = Wbase[(size_t)oc * (NCH * 27) + (size_t)(c0 + ic) * 27 + k];
            s_w[i * 2] = w; s_w[i * 2 + 1] = w;
        }
        __syncthreads();

        #pragma unroll 1
        for (int ic = 0; ic < 8; ++ic) {
            #pragma unroll 1
            for (int kd = 0; kd < 3; ++kd) {
                #pragma unroll 1
                for (int kh = 0; kh < 3; ++kh) {
                    const float* rp = &s_in[ic * 1000 + (lz + kd) * 100 + (ly + kh) * 10];
                    float2 r0 = *(const float2*)(rp + 0);
                    float2 r1 = *(const float2*)(rp + 2);
                    float2 r2 = *(const float2*)(rp + 4);
                    float2 r3 = *(const float2*)(rp + 6);
                    float2 r4 = *(const float2*)(rp + 8);
                    u64 A[3][4];
                    A[0][0] = pack2(r0.x, r0.y); A[0][1] = pack2(r1.x, r1.y);
                    A[0][2] = pack2(r2.x, r2.y); A[0][3] = pack2(r3.x, r3.y);
                    A[1][0] = pack2(r0.y, r1.x); A[1][1] = pack2(r1.y, r2.x);
                    A[1][2] = pack2(r2.y, r3.x); A[1][3] = pack2(r3.y, r4.x);
                    A[2][0] = pack2(r1.x, r1.y); A[2][1] = pack2(r2.x, r2.y);
                    A[2][2] = pack2(r3.x, r3.y); A[2][3] = pack2(r4.x, r4.y);
                    int kb = (kd * 3 + kh) * 3;
                    const u64* wp = (const u64*)s_w + (size_t)(ic * 27 + kb) * OC1 + och * 8;
                    #pragma unroll
                    for (int kw = 0; kw < 3; ++kw) {
                        const u64* wk = wp + kw * OC1;
                        #pragma unroll
                        for (int o = 0; o < 8; ++o) {
                            u64 w = wk[o];
                            #pragma unroll
                            for (int m = 0; m < 4; ++m) ffma2(acc[o][m], A[kw][m], w);
                        }
                    }
                }
            }
        }
        __syncthreads();
    }

    int gy = y0 + ly, gz = z0 + lz;
    #pragma unroll
    for (int o = 0; o < 8; ++o) {
        int ocg = ocb * OC1 + och * 8 + o;
        float bias = bs[cls * NHID + ocg];
        float* outp = g_actv + ((size_t)b * NHID + ocg) * VNNN
                    + (size_t)gz * VNN + (size_t)gy * VN + x0;
        float2 p0 = unpack2(acc[o][0]), p1 = unpack2(acc[o][1]);
        float2 p2 = unpack2(acc[o][2]), p3 = unpack2(acc[o][3]);
        float4 v0, v1;
        v0.x = fmaxf(p0.x + bias, 0.f); v0.y = fmaxf(p0.y + bias, 0.f);
        v0.z = fmaxf(p1.x + bias, 0.f); v0.w = fmaxf(p1.y + bias, 0.f);
        v1.x = fmaxf(p2.x + bias, 0.f); v1.y = fmaxf(p2.y + bias, 0.f);
        v1.z = fmaxf(p3.x + bias, 0.f); v1.w = fmaxf(p3.y + bias, 0.f);
        ((float4*)outp)[0] = v0;
        ((float4*)outp)[1] = v1;
    }
}

// ---------------------------------------------------------------------------
// Kernel C: gamma/beta convs (64 -> 32) fused with InstanceNorm epilogue
// grid: (216 tiles, 4 oc-blocks of 8, 8 batch); 128 threads
// thread = x-row of 8 (4 pairs) x (4 gamma oc + 4 beta oc, same oc set)
// ---------------------------------------------------------------------------
#define OC2 8
__global__ __launch_bounds__(128)
void conv2_kernel(const float* __restrict__ x,
                  const float* __restrict__ Wg, const float* __restrict__ bg,
                  const float* __restrict__ Wb, const float* __restrict__ bb,
                  const int* __restrict__ ycls, float* __restrict__ out) {
    __shared__ float s_in[8 * 1000];
    __shared__ float s_wg[8 * 27 * OC2 * 2];
    __shared__ float s_wb[8 * 27 * OC2 * 2];

    int t  = blockIdx.x;
    int tx = t % TPD, ty = (t / TPD) % TPD, tz = t / (TPD * TPD);
    int ocb = blockIdx.y;
    int b   = blockIdx.z;
    int cls = ycls[b];
    int tid = threadIdx.x;
    int row = tid & 63;
    int ly = row & 7, lz = row >> 3;
    int och = tid >> 6;                       // which 4 of the 8 oc
    int x0 = tx * TILE, y0 = ty * TILE, z0 = tz * TILE;

    u64 accg[4][4], accb[4][4];
    #pragma unroll
    for (int o = 0; o < 4; o++)
        #pragma unroll
        for (int m = 0; m < 4; m++) { accg[o][m] = 0ULL; accb[o][m] = 0ULL; }

    const float* Wgb = Wg + ((size_t)cls * NCH + (size_t)ocb * OC2) * (NHID * 27);
    const float* Wbb = Wb + ((size_t)cls * NCH + (size_t)ocb * OC2) * (NHID * 27);

    for (int c0 = 0; c0 < NHID; c0 += 8) {
        const float* ab = g_actv + ((size_t)b * NHID + c0) * VNNN;
        for (int i = tid; i < 8000; i += 128) {
            int ic = i / 1000; int r = i - ic * 1000;
            int zz = r / 100;  r -= zz * 100;
            int yy = r / 10;   int xx = r - yy * 10;
            int gz = z0 + zz - 1, gy = y0 + yy - 1, gx = x0 + xx - 1;
            float v = 0.f;
            if ((unsigned)gz < VN && (unsigned)gy < VN && (unsigned)gx < VN)
                v = ab[(size_t)ic * VNNN + gz * VNN + gy * VN + gx];
            s_in[i] = v;
        }
        for (int i = tid; i < 8 * 27 * OC2; i += 128) {
            int oc = i % OC2;
            int r  = i / OC2;
            int k  = r % 27;
            int ic = r / 27;
            size_t goff = (size_t)oc * (NHID * 27) + (size_t)(c0 + ic) * 27 + k;
            float wg = Wgb[goff];
            float wb = Wbb[goff];
            s_wg[i * 2] = wg; s_wg[i * 2 + 1] = wg;
            s_wb[i * 2] = wb; s_wb[i * 2 + 1] = wb;
        }
        __syncthreads();

        #pragma unroll 1
        for (int ic = 0; ic < 8; ++ic) {
            #pragma unroll 1
            for (int kd = 0; kd < 3; ++kd) {
                #pragma unroll 1
                for (int kh = 0; kh < 3; ++kh) {
                    const float* rp = &s_in[ic * 1000 + (lz + kd) * 100 + (ly + kh) * 10];
                    float2 r0 = *(const float2*)(rp + 0);
                    float2 r1 = *(const float2*)(rp + 2);
                    float2 r2 = *(const float2*)(rp + 4);
                    float2 r3 = *(const float2*)(rp + 6);
                    float2 r4 = *(const float2*)(rp + 8);
                    u64 A[3][4];
                    A[0][0] = pack2(r0.x, r0.y); A[0][1] = pack2(r1.x, r1.y);
                    A[0][2] = pack2(r2.x, r2.y); A[0][3] = pack2(r3.x, r3.y);
                    A[1][0] = pack2(r0.y, r1.x); A[1][1] = pack2(r1.y, r2.x);
                    A[1][2] = pack2(r2.y, r3.x); A[1][3] = pack2(r3.y, r4.x);
                    A[2][0] = pack2(r1.x, r1.y); A[2][1] = pack2(r2.x, r2.y);
                    A[2][2] = pack2(r3.x, r3.y); A[2][3] = pack2(r4.x, r4.y);
                    int kb = (kd * 3 + kh) * 3;
                    const u64* wpg = (const u64*)s_wg + (size_t)(ic * 27 + kb) * OC2 + och * 4;
                    const u64* wpb = (const u64*)s_wb + (size_t)(ic * 27 + kb) * OC2 + och * 4;
                    #pragma unroll
                    for (int kw = 0; kw < 3; ++kw) {
                        const u64* wkg = wpg + kw * OC2;
                        const u64* wkb = wpb + kw * OC2;
                        #pragma unroll
                        for (int o = 0; o < 4; ++o) {
                            u64 wg = wkg[o];
                            u64 wb = wkb[o];
                            #pragma unroll
                            for (int m = 0; m < 4; ++m) {
                                ffma2(accg[o][m], A[kw][m], wg);
                                ffma2(accb[o][m], A[kw][m], wb);
                            }
                        }
                    }
                }
            }
        }
        __syncthreads();
    }

    int gy = y0 + ly, gz = z0 + lz;
    #pragma unroll
    for (int o = 0; o < 4; ++o) {
        int ocg = ocb * OC2 + och * 4 + o;
        float bgv = bg[cls * NCH + ocg];
        float bbv = bb[cls * NCH + ocg];
        float mu  = g_mu[b * NCH + ocg];
        float rs  = g_rsig[b * NCH + ocg];
        size_t base = ((size_t)b * NCH + ocg) * VNNN
                    + (size_t)gz * VNN + (size_t)gy * VN + x0;
        const float4* xp = (const float4*)(x + base);
        float4* op = (float4*)(out + base);
        float2 g0 = unpack2(accg[o][0]), g1 = unpack2(accg[o][1]);
        float2 g2 = unpack2(accg[o][2]), g3 = unpack2(accg[o][3]);
        float2 b0 = unpack2(accb[o][0]), b1 = unpack2(accb[o][1]);
        float2 b2 = unpack2(accb[o][2]), b3 = unpack2(accb[o][3]);
        float4 xv0 = xp[0], xv1 = xp[1];
        float4 r0, r1;
        r0.x = (xv0.x - mu) * rs * (1.f + g0.x + bgv) + (b0.x + bbv);
        r0.y = (xv0.y - mu) * rs * (1.f + g0.y + bgv) + (b0.y + bbv);
        r0.z = (xv0.z - mu) * rs * (1.f + g1.x + bgv) + (b1.x + bbv);
        r0.w = (xv0.w - mu) * rs * (1.f + g1.y + bgv) + (b1.y + bbv);
        r1.x = (xv1.x - mu) * rs * (1.f + g2.x + bgv) + (b2.x + bbv);
        r1.y = (xv1.y - mu) * rs * (1.f + g2.y + bgv) + (b2.y + bbv);
        r1.z = (xv1.z - mu) * rs * (1.f + g3.x + bgv) + (b3.x + bbv);
        r1.w = (xv1.w - mu) * rs * (1.f + g3.y + bgv) + (b3.y + bbv);
        op[0] = r0;
        op[1] = r1;
    }
}

// ---------------------------------------------------------------------------
extern "C" void kernel_launch(void* const* d_in, const int* in_sizes, int n_in,
                              void* d_out, int out_size) {
    const float* x       = (const float*)d_in[0];
    const int*   y       = (const int*)d_in[1];
    const float* Wshared = (const float*)d_in[2];
    const float* bshared = (const float*)d_in[3];
    const float* Wgamma  = (const float*)d_in[4];
    const float* bgamma  = (const float*)d_in[5];
    const float* Wbeta   = (const float*)d_in[6];
    const float* bbeta   = (const float*)d_in[7];
    float* out = (float*)d_out;

    stats_kernel<<<NB * NCH, 256>>>(x);

    dim3 grid1(TPD * TPD * TPD, NHID / OC1, NB);
    conv1_kernel<<<grid1, 128>>>(x, Wshared, bshared, y);

    dim3 grid2(TPD * TPD * TPD, NCH / OC2, NB);
    conv2_kernel<<<grid2, 128>>>(x, Wgamma, bgamma, Wbeta, bbeta, y, out);
}

// round 5
// speedup vs baseline: 1.6986x; 1.6969x over previous
#include <cuda_runtime.h>
#include <cuda_bf16.h>
#include <cstdint>

typedef unsigned int u32;
typedef unsigned long long u64;

#define VN 48
#define VNN 2304
#define VNNN 110592
#define NB 8
#define SP_EPS 1e-5f
#define PD 50
#define PDD 2500
#define PDDD 125000

// ---------------- device scratch ----------------
__device__ __nv_bfloat16 g_xp_hi[(size_t)NB * PDDD * 32];
__device__ __nv_bfloat16 g_xp_lo[(size_t)NB * PDDD * 32];
__device__ __nv_bfloat16 g_a_hi[(size_t)NB * PDDD * 64];
__device__ __nv_bfloat16 g_a_lo[(size_t)NB * PDDD * 64];
__device__ __nv_bfloat16 g_w1[4 * 27 * 2 * 4096];   // conv1 B tiles, pre-swizzled (wh, wl)
__device__ __nv_bfloat16 g_w2[4 * 27 * 2 * 4096];   // conv2 B tiles
__device__ float g_mu[NB * 32];
__device__ float g_rsig[NB * 32];

// ---------------- helpers ----------------
__device__ __forceinline__ u32 smem_u32(const void* p) {
    u32 a; asm("{ .reg .u64 t; cvta.to.shared.u64 t, %1; cvt.u32.u64 %0, t; }"
               : "=r"(a) : "l"(p));
    return a;
}
__device__ __forceinline__ void cp16f(u32 dst, const void* src) {
    asm volatile("cp.async.ca.shared.global [%0], [%1], 16;" :: "r"(dst), "l"(src));
}
__device__ __forceinline__ void cp_commit() { asm volatile("cp.async.commit_group;"); }
__device__ __forceinline__ void cp_wait0()  { asm volatile("cp.async.wait_group 0;" ::: "memory"); }
__device__ __forceinline__ u32 packbf(__nv_bfloat16 a, __nv_bfloat16 b) {
    __nv_bfloat162 p(a, b); return *reinterpret_cast<u32*>(&p);
}
__device__ __forceinline__ u32 sw128(u32 off) { return off ^ ((off >> 3) & 0x70); }

__device__ __forceinline__ void ldsm4(u32* r, u32 addr) {
    asm volatile("ldmatrix.sync.aligned.m8n8.x4.shared.b16 {%0,%1,%2,%3}, [%4];"
        : "=r"(r[0]), "=r"(r[1]), "=r"(r[2]), "=r"(r[3]) : "r"(addr));
}
__device__ __forceinline__ void mma16816(float* d, const u32* a, u32 b0, u32 b1) {
    asm volatile("mma.sync.aligned.m16n8k16.row.col.f32.bf16.bf16.f32 "
        "{%0,%1,%2,%3}, {%4,%5,%6,%7}, {%8,%9}, {%0,%1,%2,%3};"
        : "+f"(d[0]), "+f"(d[1]), "+f"(d[2]), "+f"(d[3])
        : "r"(a[0]), "r"(a[1]), "r"(a[2]), "r"(a[3]), "r"(b0), "r"(b1));
}

// ---------------------------------------------------------------------------
// stats: per-(b,c) mean / rsqrt(var+eps) over 48^3
// ---------------------------------------------------------------------------
__global__ void stats_kernel(const float* __restrict__ x) {
    int bc = blockIdx.x;
    const float4* xp = reinterpret_cast<const float4*>(x + (size_t)bc * VNNN);
    float s = 0.f, ss = 0.f;
    for (int i = threadIdx.x; i < VNNN / 4; i += blockDim.x) {
        float4 v = xp[i];
        s  += v.x + v.y + v.z + v.w;
        ss += v.x*v.x + v.y*v.y + v.z*v.z + v.w*v.w;
    }
    __shared__ float sh_s[8], sh_ss[8];
    #pragma unroll
    for (int o = 16; o; o >>= 1) {
        s  += __shfl_down_sync(0xffffffffu, s, o);
        ss += __shfl_down_sync(0xffffffffu, ss, o);
    }
    int w = threadIdx.x >> 5, l = threadIdx.x & 31;
    if (l == 0) { sh_s[w] = s; sh_ss[w] = ss; }
    __syncthreads();
    if (w == 0) {
        s  = (l < 8) ? sh_s[l]  : 0.f;
        ss = (l < 8) ? sh_ss[l] : 0.f;
        #pragma unroll
        for (int o = 4; o; o >>= 1) {
            s  += __shfl_down_sync(0xffffffffu, s, o);
            ss += __shfl_down_sync(0xffffffffu, ss, o);
        }
        if (l == 0) {
            float mu  = s / (float)VNNN;
            float var = ss / (float)VNNN - mu * mu;
            g_mu[bc] = mu; g_rsig[bc] = rsqrtf(var + SP_EPS);
        }
    }
}

// ---------------------------------------------------------------------------
// transpose x -> padded channel-last bf16 hi/lo (zeros in halo)
// ---------------------------------------------------------------------------
__global__ __launch_bounds__(256)
void xpose_kernel(const float* __restrict__ x) {
    int pz = blockIdx.x, b = blockIdx.y;
    for (int c = threadIdx.x; c < PDD; c += 256) {
        int py = c / PD, px = c - py * PD;
        size_t lin = ((size_t)(b*PD + pz)*PD + py)*PD + px;
        uint4* dh = (uint4*)(g_xp_hi + lin * 32);
        uint4* dl = (uint4*)(g_xp_lo + lin * 32);
        if (pz >= 1 && pz <= 48 && py >= 1 && py <= 48 && px >= 1 && px <= 48) {
            const float* xb = x + (size_t)b*32*VNNN + (size_t)(pz-1)*VNN + (py-1)*VN + (px-1);
            u32 ph[16], pl[16];
            #pragma unroll
            for (int q = 0; q < 16; q++) {
                float v0 = xb[(size_t)(2*q)   * VNNN];
                float v1 = xb[(size_t)(2*q+1) * VNNN];
                __nv_bfloat16 h0 = __float2bfloat16(v0);
                __nv_bfloat16 l0 = __float2bfloat16(v0 - __bfloat162float(h0));
                __nv_bfloat16 h1 = __float2bfloat16(v1);
                __nv_bfloat16 l1 = __float2bfloat16(v1 - __bfloat162float(h1));
                ph[q] = packbf(h0, h1); pl[q] = packbf(l0, l1);
            }
            #pragma unroll
            for (int i = 0; i < 4; i++) { dh[i] = ((uint4*)ph)[i]; dl[i] = ((uint4*)pl)[i]; }
        } else {
            uint4 z = make_uint4(0,0,0,0);
            #pragma unroll
            for (int i = 0; i < 4; i++) { dh[i] = z; dl[i] = z; }
        }
    }
}

// zero the halo cells of g_a (interior written by conv1)
__global__ __launch_bounds__(256)
void zhalo_kernel() {
    int pz = blockIdx.x, b = blockIdx.y;
    bool ze = (pz == 0 || pz == 49);
    for (int c = threadIdx.x; c < PDD; c += 256) {
        int py = c / PD, px = c - py * PD;
        if (ze || py == 0 || py == 49 || px == 0 || px == 49) {
            size_t lin = ((size_t)(b*PD + pz)*PD + py)*PD + px;
            uint4 z = make_uint4(0,0,0,0);
            uint4* dh = (uint4*)(g_a_hi + lin * 64);
            uint4* dl = (uint4*)(g_a_lo + lin * 64);
            #pragma unroll
            for (int i = 0; i < 8; i++) { dh[i] = z; dl[i] = z; }
        }
    }
}

// ---------------------------------------------------------------------------
// Pre-swizzled B tiles (64n x 64k bf16, 128B rows, SW128 XOR swizzle)
// ---------------------------------------------------------------------------
__global__ void prepb1_kernel(const float* __restrict__ Ws) {
    int tap = blockIdx.x, cls = blockIdx.y;
    __nv_bfloat16* o0 = g_w1 + ((size_t)(cls*27 + tap)*2 + 0) * 4096;
    __nv_bfloat16* o1 = o0 + 4096;
    for (int i = threadIdx.x; i < 4096; i += 256) {
        int n = i >> 6, k = i & 63, ic = k & 31;
        float w = Ws[((size_t)(cls*64 + n)*32 + ic)*27 + tap];
        __nv_bfloat16 h = __float2bfloat16(w);
        __nv_bfloat16 l = __float2bfloat16(w - __bfloat162float(h));
        u32 sw = sw128((u32)(n*128 + k*2));
        o0[sw >> 1] = h; o1[sw >> 1] = l;
    }
}
__global__ void prepb2_kernel(const float* __restrict__ Wg, const float* __restrict__ Wb) {
    int tap = blockIdx.x, cls = blockIdx.y;
    __nv_bfloat16* o0 = g_w2 + ((size_t)(cls*27 + tap)*2 + 0) * 4096;
    __nv_bfloat16* o1 = o0 + 4096;
    for (int i = threadIdx.x; i < 4096; i += 256) {
        int n = i >> 6, k = i & 63;
        float w = (n < 32) ? Wg[((size_t)(cls*32 + n)*64 + k)*27 + tap]
                           : Wb[((size_t)(cls*32 + (n-32))*64 + k)*27 + tap];
        __nv_bfloat16 h = __float2bfloat16(w);
        __nv_bfloat16 l = __float2bfloat16(w - __bfloat162float(h));
        u32 sw = sw128((u32)(n*128 + k*2));
        o0[sw >> 1] = h; o1[sw >> 1] = l;
    }
}

// ---------------------------------------------------------------------------
// conv1: actv = relu(conv(x, Wshared[y]) + bshared[y])  32 -> 64 ch
// grid (9 mblk, 48 z, 8 b), 256 thr (8 warps). M=256, N=64, K=64 x 27 taps.
// Stage: A 32KB (256 rows x [ah32|al32]) + B 16KB (wh 8KB | wl 8KB). 2 stages.
// ---------------------------------------------------------------------------
#define C1_STAGE 49152
#define C1_DSMEM (2 * C1_STAGE + 1024)
__global__ __launch_bounds__(256, 1)
void conv1_kernel(const int* __restrict__ ycls, const float* __restrict__ bsh) {
    extern __shared__ char dsm[];
    __shared__ float s_bias[64];

    int mblk = blockIdx.x, z = blockIdx.y, b = blockIdx.z;
    int cls = ycls[b];
    int tid = threadIdx.x, wid = tid >> 5, lane = tid & 31;
    u32 base = (smem_u32(dsm) + 1023) & ~1023u;
    if (tid < 64) s_bias[tid] = bsh[cls*64 + tid];
    __syncthreads();

    int p0 = mblk * 256;

    auto do_copy = [&](int t, int s) {
        u32 As = base + (u32)s * C1_STAGE, Bs = As + 32768;
        int kd = t / 9, kh = (t / 3) % 3, kw = t % 3;
        int p = p0 + tid;
        int yy = p / 48, xx = p - yy * 48;
        size_t lin = ((size_t)(b*PD + z + kd)*PD + (yy + kh))*PD + (xx + kw);
        const char* sh = (const char*)(g_xp_hi + lin * 32);
        const char* sl = (const char*)(g_xp_lo + lin * 32);
        u32 ro = (u32)tid * 128;
        #pragma unroll
        for (int j = 0; j < 4; j++) cp16f(As + sw128(ro + j*16), sh + j*16);
        #pragma unroll
        for (int j = 0; j < 4; j++) cp16f(As + sw128(ro + 64 + j*16), sl + j*16);
        const char* bsrc = (const char*)(g_w1 + ((size_t)(cls*27 + t) * 2) * 4096);
        for (int i = tid; i < 1024; i += 256) cp16f(Bs + i*16, bsrc + i*16);
        cp_commit();
    };

    float acc[2][8][4];
    #pragma unroll
    for (int i = 0; i < 2; i++)
        #pragma unroll
        for (int j = 0; j < 8; j++)
            #pragma unroll
            for (int q = 0; q < 4; q++) acc[i][j][q] = 0.f;

    int arow = wid * 32;
    int lr = lane & 15, lc = lane >> 4;

    do_copy(0, 0);
    for (int t = 0; t < 27; t++) {
        int s = t & 1;
        cp_wait0();
        __syncthreads();
        if (t + 1 < 27) do_copy(t + 1, s ^ 1);
        u32 As = base + (u32)s * C1_STAGE, Bs = As + 32768;
        #pragma unroll
        for (int ks = 0; ks < 4; ks++) {
            u32 a[2][4];
            #pragma unroll
            for (int i = 0; i < 2; i++)
                ldsm4(a[i], As + sw128((u32)((arow + 16*i + lr)*128 + ks*32 + lc*16)));
            #pragma unroll
            for (int tm = 0; tm < 2; tm++) {
                u32 Bt = Bs + (u32)tm * 8192;
                #pragma unroll
                for (int j = 0; j < 4; j++) {
                    u32 bb[4];
                    ldsm4(bb, Bt + sw128((u32)((j*16 + lr)*128 + ks*32 + lc*16)));
                    #pragma unroll
                    for (int i = 0; i < 2; i++) {
                        mma16816(acc[i][2*j],   a[i], bb[0], bb[2]);
                        mma16816(acc[i][2*j+1], a[i], bb[1], bb[3]);
                    }
                }
            }
        }
    }

    // epilogue: bias + relu -> g_a hi/lo (channel-last)
    int qr = lane >> 2, qc = (lane & 3) * 2;
    #pragma unroll
    for (int i = 0; i < 2; i++) {
        #pragma unroll
        for (int rr = 0; rr < 2; rr++) {
            int m = arow + 16*i + 8*rr + qr;
            int p = p0 + m;
            int yy = p / 48, xx = p - yy * 48;
            size_t lin = ((size_t)(b*PD + z + 1)*PD + (yy + 1))*PD + (xx + 1);
            #pragma unroll
            for (int j = 0; j < 8; j++) {
                int ch = j*8 + qc;
                float v0 = fmaxf(acc[i][j][rr*2 + 0] + s_bias[ch],     0.f);
                float v1 = fmaxf(acc[i][j][rr*2 + 1] + s_bias[ch + 1], 0.f);
                __nv_bfloat16 h0 = __float2bfloat16(v0);
                __nv_bfloat16 l0 = __float2bfloat16(v0 - __bfloat162float(h0));
                __nv_bfloat16 h1 = __float2bfloat16(v1);
                __nv_bfloat16 l1 = __float2bfloat16(v1 - __bfloat162float(h1));
                *(u32*)(g_a_hi + lin*64 + ch) = packbf(h0, h1);
                *(u32*)(g_a_lo + lin*64 + ch) = packbf(l0, l1);
            }
        }
    }
}

// ---------------------------------------------------------------------------
// conv2: gamma|beta = conv(actv, [Wg;Wb][y]) (64 -> 64) + InstanceNorm epilogue
// Stage: A_H 32KB + A_L 32KB + B 16KB = 80KB. 2 stages.
// ---------------------------------------------------------------------------
#define C2_STAGE 81920
#define C2_DSMEM (2 * C2_STAGE + 1024)
__global__ __launch_bounds__(256, 1)
void conv2_kernel(const float* __restrict__ x,
                  const float* __restrict__ bg, const float* __restrict__ bb_,
                  const int* __restrict__ ycls, float* __restrict__ out) {
    extern __shared__ char dsm[];
    __shared__ float s_mu[32], s_rs[32], s_bg[32], s_bb[32];

    int mblk = blockIdx.x, z = blockIdx.y, b = blockIdx.z;
    int cls = ycls[b];
    int tid = threadIdx.x, wid = tid >> 5, lane = tid & 31;
    u32 base = (smem_u32(dsm) + 1023) & ~1023u;
    if (tid < 32) {
        s_mu[tid] = g_mu[b*32 + tid];
        s_rs[tid] = g_rsig[b*32 + tid];
        s_bg[tid] = bg[cls*32 + tid];
        s_bb[tid] = bb_[cls*32 + tid];
    }
    __syncthreads();

    int p0 = mblk * 256;

    auto do_copy = [&](int t, int s) {
        u32 AH = base + (u32)s * C2_STAGE;
        u32 AL = AH + 32768;
        u32 Bs = AH + 65536;
        int kd = t / 9, kh = (t / 3) % 3, kw = t % 3;
        int p = p0 + tid;
        int yy = p / 48, xx = p - yy * 48;
        size_t lin = ((size_t)(b*PD + z + kd)*PD + (yy + kh))*PD + (xx + kw);
        const char* sh = (const char*)(g_a_hi + lin * 64);
        const char* sl = (const char*)(g_a_lo + lin * 64);
        u32 ro = (u32)tid * 128;
        #pragma unroll
        for (int j = 0; j < 8; j++) {
            u32 sw = sw128(ro + j*16);
            cp16f(AH + sw, sh + j*16);
            cp16f(AL + sw, sl + j*16);
        }
        const char* bsrc = (const char*)(g_w2 + ((size_t)(cls*27 + t) * 2) * 4096);
        for (int i = tid; i < 1024; i += 256) cp16f(Bs + i*16, bsrc + i*16);
        cp_commit();
    };

    float acc[2][8][4];
    #pragma unroll
    for (int i = 0; i < 2; i++)
        #pragma unroll
        for (int j = 0; j < 8; j++)
            #pragma unroll
            for (int q = 0; q < 4; q++) acc[i][j][q] = 0.f;

    int arow = wid * 32;
    int lr = lane & 15, lc = lane >> 4;

    do_copy(0, 0);
    for (int t = 0; t < 27; t++) {
        int s = t & 1;
        cp_wait0();
        __syncthreads();
        if (t + 1 < 27) do_copy(t + 1, s ^ 1);
        u32 AH = base + (u32)s * C2_STAGE;
        u32 Bs = AH + 65536;
        #pragma unroll
        for (int ks = 0; ks < 4; ks++) {
            u32 a[2][2][4];   // [sub H/L][m16 block]
            #pragma unroll
            for (int sub = 0; sub < 2; sub++)
                #pragma unroll
                for (int i = 0; i < 2; i++)
                    ldsm4(a[sub][i], AH + (u32)sub*32768
                          + sw128((u32)((arow + 16*i + lr)*128 + ks*32 + lc*16)));
            #pragma unroll
            for (int tm = 0; tm < 2; tm++) {
                u32 Bt = Bs + (u32)tm * 8192;
                #pragma unroll
                for (int j = 0; j < 4; j++) {
                    u32 bb[4];
                    ldsm4(bb, Bt + sw128((u32)((j*16 + lr)*128 + ks*32 + lc*16)));
                    #pragma unroll
                    for (int sub = 0; sub < 2; sub++)
                        #pragma unroll
                        for (int i = 0; i < 2; i++) {
                            mma16816(acc[i][2*j],   a[sub][i], bb[0], bb[2]);
                            mma16816(acc[i][2*j+1], a[sub][i], bb[1], bb[3]);
                        }
                }
            }
        }
    }

    // epilogue: n<32 -> gamma[n], n>=32 -> beta[n-32]; InstanceNorm combine
    int qr = lane >> 2, qc = (lane & 3) * 2;
    #pragma unroll
    for (int i = 0; i < 2; i++) {
        #pragma unroll
        for (int rr = 0; rr < 2; rr++) {
            int m = arow + 16*i + 8*rr + qr;
            int p = p0 + m;
            int yy = p / 48, xx = p - yy * 48;
            size_t sidx = (size_t)b*32*VNNN + (size_t)z*VNN + yy*VN + xx;
            #pragma unroll
            for (int j = 0; j < 4; j++) {
                #pragma unroll
                for (int q = 0; q < 2; q++) {
                    int ch = j*8 + qc + q;
                    float gm = acc[i][j][rr*2 + q]     + s_bg[ch];
                    float bt = acc[i][j + 4][rr*2 + q] + s_bb[ch];
                    float xv = x[sidx + (size_t)ch * VNNN];
                    out[sidx + (size_t)ch * VNNN] =
                        (xv - s_mu[ch]) * s_rs[ch] * (1.f + gm) + bt;
                }
            }
        }
    }
}

// ---------------------------------------------------------------------------
extern "C" void kernel_launch(void* const* d_in, const int* in_sizes, int n_in,
                              void* d_out, int out_size) {
    const float* x       = (const float*)d_in[0];
    const int*   y       = (const int*)d_in[1];
    const float* Wshared = (const float*)d_in[2];
    const float* Wgamma  = (const float*)d_in[4];
    const float* bgamma  = (const float*)d_in[5];
    const float* Wbeta   = (const float*)d_in[6];
    const float* bbeta   = (const float*)d_in[7];
    const float* bshared = (const float*)d_in[3];
    float* out = (float*)d_out;

    cudaFuncSetAttribute(conv1_kernel, cudaFuncAttributeMaxDynamicSharedMemorySize, C1_DSMEM);
    cudaFuncSetAttribute(conv2_kernel, cudaFuncAttributeMaxDynamicSharedMemorySize, C2_DSMEM);

    stats_kernel<<<NB * 32, 256>>>(x);
    xpose_kernel<<<dim3(PD, NB), 256>>>(x);
    zhalo_kernel<<<dim3(PD, NB), 256>>>();
    prepb1_kernel<<<dim3(27, 4), 256>>>(Wshared);
    prepb2_kernel<<<dim3(27, 4), 256>>>(Wgamma, Wbeta);

    conv1_kernel<<<dim3(9, 48, NB), 256, C1_DSMEM>>>(y, bshared);
    conv2_kernel<<<dim3(9, 48, NB), 256, C2_DSMEM>>>(x, bgamma, bbeta, y, out);
}

// round 6
// speedup vs baseline: 2.4638x; 1.4505x over previous
#include <cuda_runtime.h>
#include <cuda_bf16.h>
#include <cstdint>

typedef unsigned int u32;
typedef unsigned long long u64;

#define VN 48
#define VNN 2304
#define VNNN 110592
#define NB 8
#define SP_EPS 1e-5f
#define PD 50
#define PDD 2500
#define PDDD 125000
#define XOFF 128          // guard rows before/after padded data
#define NTILE 10          // M-tiles per z-slice (250 positions each)
#define MT 250
#define AROWS 358         // 250(+6 junk) + 102 tap span + margin

// ---------------- device scratch ----------------
__device__ __nv_bfloat16 g_xp_hi[((size_t)NB * PDDD + 2 * XOFF) * 32];
__device__ __nv_bfloat16 g_xp_lo[((size_t)NB * PDDD + 2 * XOFF) * 32];
__device__ __nv_bfloat16 g_a_hi[((size_t)NB * PDDD + 2 * XOFF) * 64];
__device__ __nv_bfloat16 g_a_lo[((size_t)NB * PDDD + 2 * XOFF) * 64];
__device__ __nv_bfloat16 g_w1[4 * 27 * 2 * 4096];
__device__ __nv_bfloat16 g_w2[4 * 27 * 2 * 4096];
__device__ float g_mu[NB * 32];
__device__ float g_rsig[NB * 32];

// ---------------- helpers ----------------
__device__ __forceinline__ u32 smem_u32(const void* p) {
    u32 a; asm("{ .reg .u64 t; cvta.to.shared.u64 t, %1; cvt.u32.u64 %0, t; }"
               : "=r"(a) : "l"(p));
    return a;
}
__device__ __forceinline__ void cp16f(u32 dst, const void* src) {
    asm volatile("cp.async.ca.shared.global [%0], [%1], 16;" :: "r"(dst), "l"(src));
}
__device__ __forceinline__ void cp_commit() { asm volatile("cp.async.commit_group;"); }
__device__ __forceinline__ void cp_wait0()  { asm volatile("cp.async.wait_group 0;" ::: "memory"); }
__device__ __forceinline__ u32 packbf(__nv_bfloat16 a, __nv_bfloat16 b) {
    __nv_bfloat162 p(a, b); return *reinterpret_cast<u32*>(&p);
}
__device__ __forceinline__ u32 sw128(u32 off) { return off ^ ((off >> 3) & 0x70); }

__device__ __forceinline__ void ldsm4(u32* r, u32 addr) {
    asm volatile("ldmatrix.sync.aligned.m8n8.x4.shared.b16 {%0,%1,%2,%3}, [%4];"
        : "=r"(r[0]), "=r"(r[1]), "=r"(r[2]), "=r"(r[3]) : "r"(addr));
}
__device__ __forceinline__ void mma16816(float* d, const u32* a, u32 b0, u32 b1) {
    asm volatile("mma.sync.aligned.m16n8k16.row.col.f32.bf16.bf16.f32 "
        "{%0,%1,%2,%3}, {%4,%5,%6,%7}, {%8,%9}, {%0,%1,%2,%3};"
        : "+f"(d[0]), "+f"(d[1]), "+f"(d[2]), "+f"(d[3])
        : "r"(a[0]), "r"(a[1]), "r"(a[2]), "r"(a[3]), "r"(b0), "r"(b1));
}

// ---------------------------------------------------------------------------
// stats
// ---------------------------------------------------------------------------
__global__ void stats_kernel(const float* __restrict__ x) {
    int bc = blockIdx.x;
    const float4* xp = reinterpret_cast<const float4*>(x + (size_t)bc * VNNN);
    float s = 0.f, ss = 0.f;
    for (int i = threadIdx.x; i < VNNN / 4; i += blockDim.x) {
        float4 v = xp[i];
        s  += v.x + v.y + v.z + v.w;
        ss += v.x*v.x + v.y*v.y + v.z*v.z + v.w*v.w;
    }
    __shared__ float sh_s[8], sh_ss[8];
    #pragma unroll
    for (int o = 16; o; o >>= 1) {
        s  += __shfl_down_sync(0xffffffffu, s, o);
        ss += __shfl_down_sync(0xffffffffu, ss, o);
    }
    int w = threadIdx.x >> 5, l = threadIdx.x & 31;
    if (l == 0) { sh_s[w] = s; sh_ss[w] = ss; }
    __syncthreads();
    if (w == 0) {
        s  = (l < 8) ? sh_s[l]  : 0.f;
        ss = (l < 8) ? sh_ss[l] : 0.f;
        #pragma unroll
        for (int o = 4; o; o >>= 1) {
            s  += __shfl_down_sync(0xffffffffu, s, o);
            ss += __shfl_down_sync(0xffffffffu, ss, o);
        }
        if (l == 0) {
            float mu  = s / (float)VNNN;
            float var = ss / (float)VNNN - mu * mu;
            g_mu[bc] = mu; g_rsig[bc] = rsqrtf(var + SP_EPS);
        }
    }
}

// ---------------------------------------------------------------------------
// transpose x -> padded channel-last bf16 hi/lo
// ---------------------------------------------------------------------------
__global__ __launch_bounds__(256)
void xpose_kernel(const float* __restrict__ x) {
    int pz = blockIdx.x, b = blockIdx.y;
    for (int c = threadIdx.x; c < PDD; c += 256) {
        int py = c / PD, px = c - py * PD;
        size_t lin = (size_t)XOFF + (size_t)b*PDDD + (size_t)pz*PDD + py*PD + px;
        uint4* dh = (uint4*)(g_xp_hi + lin * 32);
        uint4* dl = (uint4*)(g_xp_lo + lin * 32);
        if (pz >= 1 && pz <= 48 && py >= 1 && py <= 48 && px >= 1 && px <= 48) {
            const float* xb = x + (size_t)b*32*VNNN + (size_t)(pz-1)*VNN + (py-1)*VN + (px-1);
            u32 ph[16], pl[16];
            #pragma unroll
            for (int q = 0; q < 16; q++) {
                float v0 = xb[(size_t)(2*q)   * VNNN];
                float v1 = xb[(size_t)(2*q+1) * VNNN];
                __nv_bfloat16 h0 = __float2bfloat16(v0);
                __nv_bfloat16 l0 = __float2bfloat16(v0 - __bfloat162float(h0));
                __nv_bfloat16 h1 = __float2bfloat16(v1);
                __nv_bfloat16 l1 = __float2bfloat16(v1 - __bfloat162float(h1));
                ph[q] = packbf(h0, h1); pl[q] = packbf(l0, l1);
            }
            #pragma unroll
            for (int i = 0; i < 4; i++) { dh[i] = ((uint4*)ph)[i]; dl[i] = ((uint4*)pl)[i]; }
        } else {
            uint4 z = make_uint4(0,0,0,0);
            #pragma unroll
            for (int i = 0; i < 4; i++) { dh[i] = z; dl[i] = z; }
        }
    }
}

__global__ __launch_bounds__(256)
void zhalo_kernel() {
    int pz = blockIdx.x, b = blockIdx.y;
    bool ze = (pz == 0 || pz == 49);
    for (int c = threadIdx.x; c < PDD; c += 256) {
        int py = c / PD, px = c - py * PD;
        if (ze || py == 0 || py == 49 || px == 0 || px == 49) {
            size_t lin = (size_t)XOFF + (size_t)b*PDDD + (size_t)pz*PDD + py*PD + px;
            uint4 z = make_uint4(0,0,0,0);
            uint4* dh = (uint4*)(g_a_hi + lin * 64);
            uint4* dl = (uint4*)(g_a_lo + lin * 64);
            #pragma unroll
            for (int i = 0; i < 8; i++) { dh[i] = z; dl[i] = z; }
        }
    }
}

// ---------------------------------------------------------------------------
// Pre-swizzled B tiles
// ---------------------------------------------------------------------------
__global__ void prepb1_kernel(const float* __restrict__ Ws) {
    int tap = blockIdx.x, cls = blockIdx.y;
    __nv_bfloat16* o0 = g_w1 + ((size_t)(cls*27 + tap)*2 + 0) * 4096;
    __nv_bfloat16* o1 = o0 + 4096;
    for (int i = threadIdx.x; i < 4096; i += 256) {
        int n = i >> 6, k = i & 63, ic = k & 31;
        float w = Ws[((size_t)(cls*64 + n)*32 + ic)*27 + tap];
        __nv_bfloat16 h = __float2bfloat16(w);
        __nv_bfloat16 l = __float2bfloat16(w - __bfloat162float(h));
        u32 sw = sw128((u32)(n*128 + k*2));
        o0[sw >> 1] = h; o1[sw >> 1] = l;
    }
}
__global__ void prepb2_kernel(const float* __restrict__ Wg, const float* __restrict__ Wb) {
    int tap = blockIdx.x, cls = blockIdx.y;
    __nv_bfloat16* o0 = g_w2 + ((size_t)(cls*27 + tap)*2 + 0) * 4096;
    __nv_bfloat16* o1 = o0 + 4096;
    for (int i = threadIdx.x; i < 4096; i += 256) {
        int n = i >> 6, k = i & 63;
        float w = (n < 32) ? Wg[((size_t)(cls*32 + n)*64 + k)*27 + tap]
                           : Wb[((size_t)(cls*32 + (n-32))*64 + k)*27 + tap];
        __nv_bfloat16 h = __float2bfloat16(w);
        __nv_bfloat16 l = __float2bfloat16(w - __bfloat162float(h));
        u32 sw = sw128((u32)(n*128 + k*2));
        o0[sw >> 1] = h; o1[sw >> 1] = l;
    }
}

// ---------------------------------------------------------------------------
// conv1: 32->64 ch. grid (10 tiles, 48 pz, 8 b), 256 thr.
// A block = 358 rows x 128B serves 9 (kh,kw) taps of one kd; 3 kd groups.
// ---------------------------------------------------------------------------
#define C1_ASTG 46080
#define C1_BSTG 16384
#define C1_DSMEM (2*C1_ASTG + 2*C1_BSTG + 1024)
__global__ __launch_bounds__(256, 1)
void conv1_kernel(const int* __restrict__ ycls, const float* __restrict__ bsh) {
    extern __shared__ char dsm[];
    __shared__ float s_bias[64];

    int tile = blockIdx.x, pz = blockIdx.y + 1, b = blockIdx.z;
    int cls = ycls[b];
    int tid = threadIdx.x, wid = tid >> 5, lane = tid & 31;
    u32 base = (smem_u32(dsm) + 1023) & ~1023u;
    if (tid < 64) s_bias[tid] = bsh[cls*64 + tid];
    __syncthreads();

    int q0 = tile * MT;
    size_t brow = (size_t)XOFF + (size_t)b*PDDD + (size_t)pz*PDD + q0;

    auto copyA = [&](int kd, int s) {
        u32 As = base + (u32)s * C1_ASTG;
        size_t blk = brow + (size_t)(kd - 1) * PDD - 51;
        for (int i = tid; i < AROWS * 8; i += 256) {
            int r = i >> 3, j = i & 7;
            u32 dst = As + sw128((u32)(r*128 + j*16));
            const char* src = (j < 4)
                ? (const char*)(g_xp_hi + (blk + r) * 32) + j*16
                : (const char*)(g_xp_lo + (blk + r) * 32) + (j-4)*16;
            cp16f(dst, src);
        }
    };
    auto copyB = [&](int t, int s) {
        u32 Bs = base + 2*C1_ASTG + (u32)s * C1_BSTG;
        const char* bsrc = (const char*)(g_w1 + ((size_t)(cls*27 + t) * 2) * 4096);
        for (int i = tid; i < 1024; i += 256) cp16f(Bs + i*16, bsrc + i*16);
    };

    float acc[2][8][4];
    #pragma unroll
    for (int i = 0; i < 2; i++)
        #pragma unroll
        for (int j = 0; j < 8; j++)
            #pragma unroll
            for (int q = 0; q < 4; q++) acc[i][j][q] = 0.f;

    int arow = wid * 32;
    int lr = lane & 15, lc = lane >> 4;

    copyA(0, 0); copyB(0, 0); cp_commit();
    for (int t = 0; t < 27; t++) {
        int kd = t / 9, kh = (t % 9) / 3, kw = t % 3;
        cp_wait0();
        __syncthreads();
        if (t + 1 < 27) {
            if ((t + 1) % 9 == 0) copyA(kd + 1, (kd + 1) & 1);
            copyB(t + 1, (t + 1) & 1);
            cp_commit();
        }
        u32 As = base + (u32)(kd & 1) * C1_ASTG;
        u32 Bs = base + 2*C1_ASTG + (u32)(t & 1) * C1_BSTG;
        int rowoff = kh * 50 + kw;
        #pragma unroll
        for (int ks = 0; ks < 4; ks++) {
            u32 a[2][4];
            #pragma unroll
            for (int i = 0; i < 2; i++)
                ldsm4(a[i], As + sw128((u32)((arow + 16*i + lr + rowoff)*128 + ks*32 + lc*16)));
            #pragma unroll
            for (int tm = 0; tm < 2; tm++) {
                u32 Bt = Bs + (u32)tm * 8192;
                #pragma unroll
                for (int j = 0; j < 4; j++) {
                    u32 bb[4];
                    ldsm4(bb, Bt + sw128((u32)((j*16 + lr)*128 + ks*32 + lc*16)));
                    #pragma unroll
                    for (int i = 0; i < 2; i++) {
                        mma16816(acc[i][2*j],   a[i], bb[0], bb[2]);
                        mma16816(acc[i][2*j+1], a[i], bb[1], bb[3]);
                    }
                }
            }
        }
    }

    // epilogue: bias + relu -> g_a (valid interior rows only)
    int qr = lane >> 2, qc = (lane & 3) * 2;
    #pragma unroll
    for (int i = 0; i < 2; i++) {
        #pragma unroll
        for (int rr = 0; rr < 2; rr++) {
            int m = arow + 16*i + 8*rr + qr;
            if (m >= MT) continue;
            int q = q0 + m;
            int py = q / 50, px = q - py * 50;
            if (py < 1 || py > 48 || px < 1 || px > 48) continue;
            size_t lin = (size_t)XOFF + (size_t)b*PDDD + (size_t)pz*PDD + q;
            #pragma unroll
            for (int j = 0; j < 8; j++) {
                int ch = j*8 + qc;
                float v0 = fmaxf(acc[i][j][rr*2 + 0] + s_bias[ch],     0.f);
                float v1 = fmaxf(acc[i][j][rr*2 + 1] + s_bias[ch + 1], 0.f);
                __nv_bfloat16 h0 = __float2bfloat16(v0);
                __nv_bfloat16 l0 = __float2bfloat16(v0 - __bfloat162float(h0));
                __nv_bfloat16 h1 = __float2bfloat16(v1);
                __nv_bfloat16 l1 = __float2bfloat16(v1 - __bfloat162float(h1));
                *(u32*)(g_a_hi + lin*64 + ch) = packbf(h0, h1);
                *(u32*)(g_a_lo + lin*64 + ch) = packbf(l0, l1);
            }
        }
    }
}

// ---------------------------------------------------------------------------
// conv2: 64->64(gamma|beta) + InstanceNorm epilogue. Same tiling.
// A stage = hi block (358 rows) + lo block. Drops al*wl term.
// ---------------------------------------------------------------------------
#define C2_ASTG 92160
#define C2_BSTG 16384
#define C2_DSMEM (2*C2_ASTG + 2*C2_BSTG + 1024)
__global__ __launch_bounds__(256, 1)
void conv2_kernel(const float* __restrict__ x,
                  const float* __restrict__ bg, const float* __restrict__ bb_,
                  const int* __restrict__ ycls, float* __restrict__ out) {
    extern __shared__ char dsm[];
    __shared__ float s_mu[32], s_rs[32], s_bg[32], s_bb[32];

    int tile = blockIdx.x, pz = blockIdx.y + 1, b = blockIdx.z;
    int cls = ycls[b];
    int tid = threadIdx.x, wid = tid >> 5, lane = tid & 31;
    u32 base = (smem_u32(dsm) + 1023) & ~1023u;
    if (tid < 32) {
        s_mu[tid] = g_mu[b*32 + tid];
        s_rs[tid] = g_rsig[b*32 + tid];
        s_bg[tid] = bg[cls*32 + tid];
        s_bb[tid] = bb_[cls*32 + tid];
    }
    __syncthreads();

    int q0 = tile * MT;
    size_t brow = (size_t)XOFF + (size_t)b*PDDD + (size_t)pz*PDD + q0;

    auto copyA = [&](int kd, int s) {
        u32 AH = base + (u32)s * C2_ASTG;
        u32 AL = AH + C1_ASTG;   // 46080 inside stage
        size_t blk = brow + (size_t)(kd - 1) * PDD - 51;
        for (int i = tid; i < AROWS * 8; i += 256) {
            int r = i >> 3, j = i & 7;
            u32 sw = sw128((u32)(r*128 + j*16));
            cp16f(AH + sw, (const char*)(g_a_hi + (blk + r) * 64) + j*16);
            cp16f(AL + sw, (const char*)(g_a_lo + (blk + r) * 64) + j*16);
        }
    };
    auto copyB = [&](int t, int s) {
        u32 Bs = base + 2*C2_ASTG + (u32)s * C2_BSTG;
        const char* bsrc = (const char*)(g_w2 + ((size_t)(cls*27 + t) * 2) * 4096);
        for (int i = tid; i < 1024; i += 256) cp16f(Bs + i*16, bsrc + i*16);
    };

    float acc[2][8][4];
    #pragma unroll
    for (int i = 0; i < 2; i++)
        #pragma unroll
        for (int j = 0; j < 8; j++)
            #pragma unroll
            for (int q = 0; q < 4; q++) acc[i][j][q] = 0.f;

    int arow = wid * 32;
    int lr = lane & 15, lc = lane >> 4;

    copyA(0, 0); copyB(0, 0); cp_commit();
    for (int t = 0; t < 27; t++) {
        int kd = t / 9, kh = (t % 9) / 3, kw = t % 3;
        cp_wait0();
        __syncthreads();
        if (t + 1 < 27) {
            if ((t + 1) % 9 == 0) copyA(kd + 1, (kd + 1) & 1);
            copyB(t + 1, (t + 1) & 1);
            cp_commit();
        }
        u32 AH = base + (u32)(kd & 1) * C2_ASTG;
        u32 AL = AH + C1_ASTG;
        u32 Bs = base + 2*C2_ASTG + (u32)(t & 1) * C2_BSTG;
        int rowoff = kh * 50 + kw;
        #pragma unroll
        for (int ks = 0; ks < 4; ks++) {
            u32 aH[2][4], aL[2][4];
            #pragma unroll
            for (int i = 0; i < 2; i++) {
                u32 sw = sw128((u32)((arow + 16*i + lr + rowoff)*128 + ks*32 + lc*16));
                ldsm4(aH[i], AH + sw);
                ldsm4(aL[i], AL + sw);
            }
            #pragma unroll
            for (int tm = 0; tm < 2; tm++) {
                u32 Bt = Bs + (u32)tm * 8192;
                #pragma unroll
                for (int j = 0; j < 4; j++) {
                    u32 bb[4];
                    ldsm4(bb, Bt + sw128((u32)((j*16 + lr)*128 + ks*32 + lc*16)));
                    #pragma unroll
                    for (int i = 0; i < 2; i++) {
                        mma16816(acc[i][2*j],   aH[i], bb[0], bb[2]);
                        mma16816(acc[i][2*j+1], aH[i], bb[1], bb[3]);
                    }
                    if (tm == 0) {
                        #pragma unroll
                        for (int i = 0; i < 2; i++) {
                            mma16816(acc[i][2*j],   aL[i], bb[0], bb[2]);
                            mma16816(acc[i][2*j+1], aL[i], bb[1], bb[3]);
                        }
                    }
                }
            }
        }
    }

    // epilogue
    int qr = lane >> 2, qc = (lane & 3) * 2;
    #pragma unroll
    for (int i = 0; i < 2; i++) {
        #pragma unroll
        for (int rr = 0; rr < 2; rr++) {
            int m = arow + 16*i + 8*rr + qr;
            if (m >= MT) continue;
            int q = q0 + m;
            int py = q / 50, px = q - py * 50;
            if (py < 1 || py > 48 || px < 1 || px > 48) continue;
            size_t sidx = (size_t)b*32*VNNN + (size_t)(pz-1)*VNN + (py-1)*VN + (px-1);
            #pragma unroll
            for (int j = 0; j < 4; j++) {
                #pragma unroll
                for (int qx = 0; qx < 2; qx++) {
                    int ch = j*8 + qc + qx;
                    float gm = acc[i][j][rr*2 + qx]     + s_bg[ch];
                    float bt = acc[i][j + 4][rr*2 + qx] + s_bb[ch];
                    float xv = x[sidx + (size_t)ch * VNNN];
                    out[sidx + (size_t)ch * VNNN] =
                        (xv - s_mu[ch]) * s_rs[ch] * (1.f + gm) + bt;
                }
            }
        }
    }
}

// ---------------------------------------------------------------------------
extern "C" void kernel_launch(void* const* d_in, const int* in_sizes, int n_in,
                              void* d_out, int out_size) {
    const float* x       = (const float*)d_in[0];
    const int*   y       = (const int*)d_in[1];
    const float* Wshared = (const float*)d_in[2];
    const float* bshared = (const float*)d_in[3];
    const float* Wgamma  = (const float*)d_in[4];
    const float* bgamma  = (const float*)d_in[5];
    const float* Wbeta   = (const float*)d_in[6];
    const float* bbeta   = (const float*)d_in[7];
    float* out = (float*)d_out;

    cudaFuncSetAttribute(conv1_kernel, cudaFuncAttributeMaxDynamicSharedMemorySize, C1_DSMEM);
    cudaFuncSetAttribute(conv2_kernel, cudaFuncAttributeMaxDynamicSharedMemorySize, C2_DSMEM);

    stats_kernel<<<NB * 32, 256>>>(x);
    xpose_kernel<<<dim3(PD, NB), 256>>>(x);
    zhalo_kernel<<<dim3(PD, NB), 256>>>();
    prepb1_kernel<<<dim3(27, 4), 256>>>(Wshared);
    prepb2_kernel<<<dim3(27, 4), 256>>>(Wgamma, Wbeta);

    conv1_kernel<<<dim3(NTILE, 48, NB), 256, C1_DSMEM>>>(y, bshared);
    conv2_kernel<<<dim3(NTILE, 48, NB), 256, C2_DSMEM>>>(x, bgamma, bbeta, y, out);
}

// round 7
// speedup vs baseline: 2.6174x; 1.0623x over previous
#include <cuda_runtime.h>
#include <cuda_bf16.h>
#include <cstdint>

typedef unsigned int u32;
typedef unsigned long long u64;

#define VN 48
#define VNN 2304
#define VNNN 110592
#define NB 8
#define SP_EPS 1e-5f
#define PD 50
#define PDD 2500
#define PDDD 125000
#define XOFF 128
#define NTILE 5
#define MT 500
#define AROWS 616         // 512 (padded M) + 102 tap span + margin

// ---------------- device scratch ----------------
__device__ __nv_bfloat16 g_xp_hi[((size_t)NB * PDDD + 2 * XOFF) * 32];
__device__ __nv_bfloat16 g_xp_lo[((size_t)NB * PDDD + 2 * XOFF) * 32];
__device__ __nv_bfloat16 g_a_hi[((size_t)NB * PDDD + 2 * XOFF) * 64];
__device__ __nv_bfloat16 g_a_lo[((size_t)NB * PDDD + 2 * XOFF) * 64];
__device__ __nv_bfloat16 g_w1[4 * 27 * 2 * 4096];
__device__ __nv_bfloat16 g_w2[4 * 27 * 2 * 4096];
__device__ float g_mu[NB * 32];
__device__ float g_rsig[NB * 32];

// ---------------- helpers ----------------
__device__ __forceinline__ u32 smem_u32(const void* p) {
    u32 a; asm("{ .reg .u64 t; cvta.to.shared.u64 t, %1; cvt.u32.u64 %0, t; }"
               : "=r"(a) : "l"(p));
    return a;
}
__device__ __forceinline__ void cp16f(u32 dst, const void* src) {
    asm volatile("cp.async.ca.shared.global [%0], [%1], 16;" :: "r"(dst), "l"(src));
}
__device__ __forceinline__ void cp_commit() { asm volatile("cp.async.commit_group;"); }
__device__ __forceinline__ void cp_wait0()  { asm volatile("cp.async.wait_group 0;" ::: "memory"); }
__device__ __forceinline__ u32 packbf(__nv_bfloat16 a, __nv_bfloat16 b) {
    __nv_bfloat162 p(a, b); return *reinterpret_cast<u32*>(&p);
}
__device__ __forceinline__ u32 sw128(u32 off) { return off ^ ((off >> 3) & 0x70); }

__device__ __forceinline__ void ldsm4(u32* r, u32 addr) {
    asm volatile("ldmatrix.sync.aligned.m8n8.x4.shared.b16 {%0,%1,%2,%3}, [%4];"
        : "=r"(r[0]), "=r"(r[1]), "=r"(r[2]), "=r"(r[3]) : "r"(addr));
}
__device__ __forceinline__ void mma16816(float* d, const u32* a, u32 b0, u32 b1) {
    asm volatile("mma.sync.aligned.m16n8k16.row.col.f32.bf16.bf16.f32 "
        "{%0,%1,%2,%3}, {%4,%5,%6,%7}, {%8,%9}, {%0,%1,%2,%3};"
        : "+f"(d[0]), "+f"(d[1]), "+f"(d[2]), "+f"(d[3])
        : "r"(a[0]), "r"(a[1]), "r"(a[2]), "r"(a[3]), "r"(b0), "r"(b1));
}

// ---------------------------------------------------------------------------
// stats
// ---------------------------------------------------------------------------
__global__ void stats_kernel(const float* __restrict__ x) {
    int bc = blockIdx.x;
    const float4* xp = reinterpret_cast<const float4*>(x + (size_t)bc * VNNN);
    float s = 0.f, ss = 0.f;
    for (int i = threadIdx.x; i < VNNN / 4; i += blockDim.x) {
        float4 v = xp[i];
        s  += v.x + v.y + v.z + v.w;
        ss += v.x*v.x + v.y*v.y + v.z*v.z + v.w*v.w;
    }
    __shared__ float sh_s[8], sh_ss[8];
    #pragma unroll
    for (int o = 16; o; o >>= 1) {
        s  += __shfl_down_sync(0xffffffffu, s, o);
        ss += __shfl_down_sync(0xffffffffu, ss, o);
    }
    int w = threadIdx.x >> 5, l = threadIdx.x & 31;
    if (l == 0) { sh_s[w] = s; sh_ss[w] = ss; }
    __syncthreads();
    if (w == 0) {
        s  = (l < 8) ? sh_s[l]  : 0.f;
        ss = (l < 8) ? sh_ss[l] : 0.f;
        #pragma unroll
        for (int o = 4; o; o >>= 1) {
            s  += __shfl_down_sync(0xffffffffu, s, o);
            ss += __shfl_down_sync(0xffffffffu, ss, o);
        }
        if (l == 0) {
            float mu  = s / (float)VNNN;
            float var = ss / (float)VNNN - mu * mu;
            g_mu[bc] = mu; g_rsig[bc] = rsqrtf(var + SP_EPS);
        }
    }
}

// ---------------------------------------------------------------------------
// transpose x -> padded channel-last bf16 hi/lo
// ---------------------------------------------------------------------------
__global__ __launch_bounds__(256)
void xpose_kernel(const float* __restrict__ x) {
    int pz = blockIdx.x, b = blockIdx.y;
    for (int c = threadIdx.x; c < PDD; c += 256) {
        int py = c / PD, px = c - py * PD;
        size_t lin = (size_t)XOFF + (size_t)b*PDDD + (size_t)pz*PDD + py*PD + px;
        uint4* dh = (uint4*)(g_xp_hi + lin * 32);
        uint4* dl = (uint4*)(g_xp_lo + lin * 32);
        if (pz >= 1 && pz <= 48 && py >= 1 && py <= 48 && px >= 1 && px <= 48) {
            const float* xb = x + (size_t)b*32*VNNN + (size_t)(pz-1)*VNN + (py-1)*VN + (px-1);
            u32 ph[16], pl[16];
            #pragma unroll
            for (int q = 0; q < 16; q++) {
                float v0 = xb[(size_t)(2*q)   * VNNN];
                float v1 = xb[(size_t)(2*q+1) * VNNN];
                __nv_bfloat16 h0 = __float2bfloat16(v0);
                __nv_bfloat16 l0 = __float2bfloat16(v0 - __bfloat162float(h0));
                __nv_bfloat16 h1 = __float2bfloat16(v1);
                __nv_bfloat16 l1 = __float2bfloat16(v1 - __bfloat162float(h1));
                ph[q] = packbf(h0, h1); pl[q] = packbf(l0, l1);
            }
            #pragma unroll
            for (int i = 0; i < 4; i++) { dh[i] = ((uint4*)ph)[i]; dl[i] = ((uint4*)pl)[i]; }
        } else {
            uint4 z = make_uint4(0,0,0,0);
            #pragma unroll
            for (int i = 0; i < 4; i++) { dh[i] = z; dl[i] = z; }
        }
    }
}

__global__ __launch_bounds__(256)
void zhalo_kernel() {
    int pz = blockIdx.x, b = blockIdx.y;
    bool ze = (pz == 0 || pz == 49);
    for (int c = threadIdx.x; c < PDD; c += 256) {
        int py = c / PD, px = c - py * PD;
        if (ze || py == 0 || py == 49 || px == 0 || px == 49) {
            size_t lin = (size_t)XOFF + (size_t)b*PDDD + (size_t)pz*PDD + py*PD + px;
            uint4 z = make_uint4(0,0,0,0);
            uint4* dh = (uint4*)(g_a_hi + lin * 64);
            uint4* dl = (uint4*)(g_a_lo + lin * 64);
            #pragma unroll
            for (int i = 0; i < 8; i++) { dh[i] = z; dl[i] = z; }
        }
    }
}

// ---------------------------------------------------------------------------
// Pre-swizzled B tiles
// ---------------------------------------------------------------------------
__global__ void prepb1_kernel(const float* __restrict__ Ws) {
    int tap = blockIdx.x, cls = blockIdx.y;
    __nv_bfloat16* o0 = g_w1 + ((size_t)(cls*27 + tap)*2 + 0) * 4096;
    __nv_bfloat16* o1 = o0 + 4096;
    for (int i = threadIdx.x; i < 4096; i += 256) {
        int n = i >> 6, k = i & 63, ic = k & 31;
        float w = Ws[((size_t)(cls*64 + n)*32 + ic)*27 + tap];
        __nv_bfloat16 h = __float2bfloat16(w);
        __nv_bfloat16 l = __float2bfloat16(w - __bfloat162float(h));
        u32 sw = sw128((u32)(n*128 + k*2));
        o0[sw >> 1] = h; o1[sw >> 1] = l;
    }
}
__global__ void prepb2_kernel(const float* __restrict__ Wg, const float* __restrict__ Wb) {
    int tap = blockIdx.x, cls = blockIdx.y;
    __nv_bfloat16* o0 = g_w2 + ((size_t)(cls*27 + tap)*2 + 0) * 4096;
    __nv_bfloat16* o1 = o0 + 4096;
    for (int i = threadIdx.x; i < 4096; i += 256) {
        int n = i >> 6, k = i & 63;
        float w = (n < 32) ? Wg[((size_t)(cls*32 + n)*64 + k)*27 + tap]
                           : Wb[((size_t)(cls*32 + (n-32))*64 + k)*27 + tap];
        __nv_bfloat16 h = __float2bfloat16(w);
        __nv_bfloat16 l = __float2bfloat16(w - __bfloat162float(h));
        u32 sw = sw128((u32)(n*128 + k*2));
        o0[sw >> 1] = h; o1[sw >> 1] = l;
    }
}

// ---------------------------------------------------------------------------
// conv1: 32->64 ch. grid (5 tiles, 48 pz, 8 b), 512 thr (16 warps, 8m x 2n).
// A dbuf (616 rows x 128B per stage), B dbuf 16KB.
// ---------------------------------------------------------------------------
#define ASTG (AROWS * 128)
#define BSTG1 16384
#define C1_DSMEM (2*ASTG + 2*BSTG1 + 1024)
__global__ __launch_bounds__(512, 1)
void conv1_kernel(const int* __restrict__ ycls, const float* __restrict__ bsh) {
    extern __shared__ char dsm[];
    __shared__ float s_bias[64];

    int tile = blockIdx.x, pz = blockIdx.y + 1, b = blockIdx.z;
    int cls = ycls[b];
    int tid = threadIdx.x, wid = tid >> 5, lane = tid & 31;
    u32 base = (smem_u32(dsm) + 1023) & ~1023u;
    if (tid < 64) s_bias[tid] = bsh[cls*64 + tid];
    __syncthreads();

    int q0 = tile * MT;
    size_t brow = (size_t)XOFF + (size_t)b*PDDD + (size_t)pz*PDD + q0;

    auto copyA = [&](int kd, int s) {
        u32 As = base + (u32)s * ASTG;
        size_t blk = brow + (size_t)(kd - 1) * PDD - 51;
        for (int i = tid; i < AROWS * 8; i += 512) {
            int r = i >> 3, j = i & 7;
            u32 dst = As + sw128((u32)(r*128 + j*16));
            const char* src = (j < 4)
                ? (const char*)(g_xp_hi + (blk + r) * 32) + j*16
                : (const char*)(g_xp_lo + (blk + r) * 32) + (j-4)*16;
            cp16f(dst, src);
        }
    };
    auto copyB = [&](int t, int s) {
        u32 Bs = base + 2*ASTG + (u32)s * BSTG1;
        const char* bsrc = (const char*)(g_w1 + ((size_t)(cls*27 + t) * 2) * 4096);
        for (int i = tid; i < 1024; i += 512) cp16f(Bs + i*16, bsrc + i*16);
    };

    float acc[4][4][4];
    #pragma unroll
    for (int i = 0; i < 4; i++)
        #pragma unroll
        for (int j = 0; j < 4; j++)
            #pragma unroll
            for (int q = 0; q < 4; q++) acc[i][j][q] = 0.f;

    int arow = (wid >> 1) * 64;
    int nslot = wid & 1;
    int lr = lane & 15, lc = lane >> 4;

    copyA(0, 0); copyB(0, 0); cp_commit();
    for (int t = 0; t < 27; t++) {
        int kd = t / 9, kh = (t % 9) / 3, kw = t % 3;
        cp_wait0();
        __syncthreads();
        if (t + 1 < 27) {
            if ((t + 1) % 9 == 0) copyA(kd + 1, (kd + 1) & 1);
            copyB(t + 1, (t + 1) & 1);
            cp_commit();
        }
        u32 As = base + (u32)(kd & 1) * ASTG;
        u32 Bs = base + 2*ASTG + (u32)(t & 1) * BSTG1;
        int rowoff = kh * 50 + kw;
        #pragma unroll
        for (int ks = 0; ks < 4; ks++) {
            u32 a[4][4];
            #pragma unroll
            for (int i = 0; i < 4; i++)
                ldsm4(a[i], As + sw128((u32)((arow + 16*i + lr + rowoff)*128 + ks*32 + lc*16)));
            #pragma unroll
            for (int tm = 0; tm < 2; tm++) {
                u32 Bt = Bs + (u32)tm * 8192;
                #pragma unroll
                for (int j = 0; j < 2; j++) {
                    u32 bb[4];
                    ldsm4(bb, Bt + sw128((u32)((nslot*32 + j*16 + lr)*128 + ks*32 + lc*16)));
                    #pragma unroll
                    for (int i = 0; i < 4; i++) {
                        mma16816(acc[i][2*j],   a[i], bb[0], bb[2]);
                        mma16816(acc[i][2*j+1], a[i], bb[1], bb[3]);
                    }
                }
            }
        }
    }

    // epilogue: bias + relu -> g_a
    int qr = lane >> 2, qc = (lane & 3) * 2;
    #pragma unroll
    for (int i = 0; i < 4; i++) {
        #pragma unroll
        for (int rr = 0; rr < 2; rr++) {
            int m = arow + 16*i + 8*rr + qr;
            if (m >= MT) continue;
            int q = q0 + m;
            int py = q / 50, px = q - py * 50;
            if (py < 1 || py > 48 || px < 1 || px > 48) continue;
            size_t lin = (size_t)XOFF + (size_t)b*PDDD + (size_t)pz*PDD + q;
            #pragma unroll
            for (int jj = 0; jj < 4; jj++) {
                int ch = nslot*32 + jj*8 + qc;
                float v0 = fmaxf(acc[i][jj][rr*2 + 0] + s_bias[ch],     0.f);
                float v1 = fmaxf(acc[i][jj][rr*2 + 1] + s_bias[ch + 1], 0.f);
                __nv_bfloat16 h0 = __float2bfloat16(v0);
                __nv_bfloat16 l0 = __float2bfloat16(v0 - __bfloat162float(h0));
                __nv_bfloat16 h1 = __float2bfloat16(v1);
                __nv_bfloat16 l1 = __float2bfloat16(v1 - __bfloat162float(h1));
                *(u32*)(g_a_hi + lin*64 + ch) = packbf(h0, h1);
                *(u32*)(g_a_lo + lin*64 + ch) = packbf(l0, l1);
            }
        }
    }
}

// ---------------------------------------------------------------------------
// conv2: 64->64 (gamma|beta) + InstanceNorm. Single-A (hi+lo), B dbuf.
// 16 warps (8m x 2n). smem-exchange epilogue for gamma/beta combine.
// ---------------------------------------------------------------------------
#define BSTG2 16384
#define C2_DSMEM (2*ASTG + 2*BSTG2 + 1024)
__global__ __launch_bounds__(512, 1)
void conv2_kernel(const float* __restrict__ x,
                  const float* __restrict__ bg, const float* __restrict__ bb_,
                  const int* __restrict__ ycls, float* __restrict__ out) {
    extern __shared__ char dsm[];
    __shared__ float s_mu[32], s_rs[32], s_bg[32], s_bb[32];

    int tile = blockIdx.x, pz = blockIdx.y + 1, b = blockIdx.z;
    int cls = ycls[b];
    int tid = threadIdx.x, wid = tid >> 5, lane = tid & 31;
    u32 base = (smem_u32(dsm) + 1023) & ~1023u;
    if (tid < 32) {
        s_mu[tid] = g_mu[b*32 + tid];
        s_rs[tid] = g_rsig[b*32 + tid];
        s_bg[tid] = bg[cls*32 + tid];
        s_bb[tid] = bb_[cls*32 + tid];
    }
    __syncthreads();

    int q0 = tile * MT;
    size_t brow = (size_t)XOFF + (size_t)b*PDDD + (size_t)pz*PDD + q0;
    u32 AH = base, AL = base + ASTG;

    auto copyA = [&](int kd) {
        size_t blk = brow + (size_t)(kd - 1) * PDD - 51;
        for (int i = tid; i < AROWS * 8; i += 512) {
            int r = i >> 3, j = i & 7;
            u32 sw = sw128((u32)(r*128 + j*16));
            cp16f(AH + sw, (const char*)(g_a_hi + (blk + r) * 64) + j*16);
            cp16f(AL + sw, (const char*)(g_a_lo + (blk + r) * 64) + j*16);
        }
    };
    auto copyB = [&](int t, int s) {
        u32 Bs = base + 2*ASTG + (u32)s * BSTG2;
        const char* bsrc = (const char*)(g_w2 + ((size_t)(cls*27 + t) * 2) * 4096);
        for (int i = tid; i < 1024; i += 512) cp16f(Bs + i*16, bsrc + i*16);
    };

    float acc[4][4][4];
    #pragma unroll
    for (int i = 0; i < 4; i++)
        #pragma unroll
        for (int j = 0; j < 4; j++)
            #pragma unroll
            for (int q = 0; q < 4; q++) acc[i][j][q] = 0.f;

    int arow = (wid >> 1) * 64;
    int nslot = wid & 1;
    int lr = lane & 15, lc = lane >> 4;

    copyA(0); copyB(0, 0); cp_commit();
    for (int t = 0; t < 27; t++) {
        int kd = t / 9, kh = (t % 9) / 3, kw = t % 3;
        cp_wait0();
        __syncthreads();
        int nt = t + 1;
        if (nt < 27 && nt % 9 != 0) { copyB(nt, nt & 1); cp_commit(); }
        u32 Bs = base + 2*ASTG + (u32)(t & 1) * BSTG2;
        int rowoff = kh * 50 + kw;
        #pragma unroll
        for (int ks = 0; ks < 4; ks++) {
            u32 aH[4][4], aL[4][4];
            #pragma unroll
            for (int i = 0; i < 4; i++) {
                u32 sw = sw128((u32)((arow + 16*i + lr + rowoff)*128 + ks*32 + lc*16));
                ldsm4(aH[i], AH + sw);
                ldsm4(aL[i], AL + sw);
            }
            #pragma unroll
            for (int tm = 0; tm < 2; tm++) {
                u32 Bt = Bs + (u32)tm * 8192;
                #pragma unroll
                for (int j = 0; j < 2; j++) {
                    u32 bb[4];
                    ldsm4(bb, Bt + sw128((u32)((nslot*32 + j*16 + lr)*128 + ks*32 + lc*16)));
                    #pragma unroll
                    for (int i = 0; i < 4; i++) {
                        mma16816(acc[i][2*j],   aH[i], bb[0], bb[2]);
                        mma16816(acc[i][2*j+1], aH[i], bb[1], bb[3]);
                    }
                    if (tm == 0) {
                        #pragma unroll
                        for (int i = 0; i < 4; i++) {
                            mma16816(acc[i][2*j],   aL[i], bb[0], bb[2]);
                            mma16816(acc[i][2*j+1], aL[i], bb[1], bb[3]);
                        }
                    }
                }
            }
        }
        if (nt < 27 && nt % 9 == 0) {
            __syncthreads();                 // all warps done reading A
            copyA(nt / 9); copyB(nt, nt & 1); cp_commit();
        }
    }

    // ---------- exchange epilogue ----------
    __syncthreads();   // done with A smem; reuse for exchange
    float* sg = (float*)(dsm + (base - smem_u32(dsm)));
    float* sb = sg + 512 * 33;

    int qr = lane >> 2, qc = (lane & 3) * 2;
    #pragma unroll
    for (int i = 0; i < 4; i++) {
        #pragma unroll
        for (int rr = 0; rr < 2; rr++) {
            int m = arow + 16*i + 8*rr + qr;
            #pragma unroll
            for (int jj = 0; jj < 4; jj++) {
                int n = nslot*32 + jj*8 + qc;
                float v0 = acc[i][jj][rr*2 + 0];
                float v1 = acc[i][jj][rr*2 + 1];
                if (n < 32) { sg[m*33 + n] = v0; sg[m*33 + n + 1] = v1; }
                else        { sb[m*33 + n - 32] = v0; sb[m*33 + n - 31] = v1; }
            }
        }
    }
    __syncthreads();

    if (tid < MT) {
        int q = q0 + tid;
        int py = q / 50, px = q - py * 50;
        if (py >= 1 && py <= 48 && px >= 1 && px <= 48) {
            size_t sidx = (size_t)b*32*VNNN + (size_t)(pz-1)*VNN + (py-1)*VN + (px-1);
            #pragma unroll 8
            for (int ch = 0; ch < 32; ch++) {
                float gm = sg[tid*33 + ch] + s_bg[ch];
                float bt = sb[tid*33 + ch] + s_bb[ch];
                float xv = x[sidx + (size_t)ch * VNNN];
                out[sidx + (size_t)ch * VNNN] =
                    (xv - s_mu[ch]) * s_rs[ch] * (1.f + gm) + bt;
            }
        }
    }
}

// ---------------------------------------------------------------------------
extern "C" void kernel_launch(void* const* d_in, const int* in_sizes, int n_in,
                              void* d_out, int out_size) {
    const float* x       = (const float*)d_in[0];
    const int*   y       = (const int*)d_in[1];
    const float* Wshared = (const float*)d_in[2];
    const float* bshared = (const float*)d_in[3];
    const float* Wgamma  = (const float*)d_in[4];
    const float* bgamma  = (const float*)d_in[5];
    const float* Wbeta   = (const float*)d_in[6];
    const float* bbeta   = (const float*)d_in[7];
    float* out = (float*)d_out;

    cudaFuncSetAttribute(conv1_kernel, cudaFuncAttributeMaxDynamicSharedMemorySize, C1_DSMEM);
    cudaFuncSetAttribute(conv2_kernel, cudaFuncAttributeMaxDynamicSharedMemorySize, C2_DSMEM);

    stats_kernel<<<NB * 32, 256>>>(x);
    xpose_kernel<<<dim3(PD, NB), 256>>>(x);
    zhalo_kernel<<<dim3(PD, NB), 256>>>();
    prepb1_kernel<<<dim3(27, 4), 256>>>(Wshared);
    prepb2_kernel<<<dim3(27, 4), 256>>>(Wgamma, Wbeta);

    conv1_kernel<<<dim3(NTILE, 48, NB), 512, C1_DSMEM>>>(y, bshared);
    conv2_kernel<<<dim3(NTILE, 48, NB), 512, C2_DSMEM>>>(x, bgamma, bbeta, y, out);
}

// round 8
// speedup vs baseline: 2.7926x; 1.0669x over previous
#include <cuda_runtime.h>
#include <cuda_bf16.h>
#include <cstdint>

typedef unsigned int u32;
typedef unsigned long long u64;

#define VN 48
#define VNN 2304
#define VNNN 110592
#define NB 8
#define SP_EPS 1e-5f
#define PD 50
#define PDD 2500
#define PDDD 125000
#define XOFF 128
#define NTILE 10
#define MT 250
#define AROWS 360

// ---------------- device scratch ----------------
__device__ __nv_bfloat16 g_xp_hi[((size_t)NB * PDDD + 2 * XOFF) * 32];
__device__ __nv_bfloat16 g_xp_lo[((size_t)NB * PDDD + 2 * XOFF) * 32];
__device__ __nv_bfloat16 g_a_hi[((size_t)NB * PDDD + 2 * XOFF) * 64];
__device__ __nv_bfloat16 g_a_lo[((size_t)NB * PDDD + 2 * XOFF) * 64];
__device__ __nv_bfloat16 g_w1[4 * 27 * 2 * 4096];
__device__ __nv_bfloat16 g_w2[4 * 27 * 2 * 4096];
__device__ float g_mu[NB * 32];
__device__ float g_rsig[NB * 32];

// ---------------- helpers ----------------
__device__ __forceinline__ u32 smem_u32(const void* p) {
    u32 a; asm("{ .reg .u64 t; cvta.to.shared.u64 t, %1; cvt.u32.u64 %0, t; }"
               : "=r"(a) : "l"(p));
    return a;
}
__device__ __forceinline__ void cp16f(u32 dst, const void* src) {
    asm volatile("cp.async.ca.shared.global [%0], [%1], 16;" :: "r"(dst), "l"(src));
}
__device__ __forceinline__ void cp_commit() { asm volatile("cp.async.commit_group;"); }
__device__ __forceinline__ void cp_wait0()  { asm volatile("cp.async.wait_group 0;" ::: "memory"); }
__device__ __forceinline__ u32 packbf(__nv_bfloat16 a, __nv_bfloat16 b) {
    __nv_bfloat162 p(a, b); return *reinterpret_cast<u32*>(&p);
}
__device__ __forceinline__ u32 sw128(u32 off) { return off ^ ((off >> 3) & 0x70); }

__device__ __forceinline__ void ldsm4(u32* r, u32 addr) {
    asm volatile("ldmatrix.sync.aligned.m8n8.x4.shared.b16 {%0,%1,%2,%3}, [%4];"
        : "=r"(r[0]), "=r"(r[1]), "=r"(r[2]), "=r"(r[3]) : "r"(addr));
}
__device__ __forceinline__ void mma16816(float* d, const u32* a, u32 b0, u32 b1) {
    asm volatile("mma.sync.aligned.m16n8k16.row.col.f32.bf16.bf16.f32 "
        "{%0,%1,%2,%3}, {%4,%5,%6,%7}, {%8,%9}, {%0,%1,%2,%3};"
        : "+f"(d[0]), "+f"(d[1]), "+f"(d[2]), "+f"(d[3])
        : "r"(a[0]), "r"(a[1]), "r"(a[2]), "r"(a[3]), "r"(b0), "r"(b1));
}

// ---------------------------------------------------------------------------
// stats
// ---------------------------------------------------------------------------
__global__ void stats_kernel(const float* __restrict__ x) {
    int bc = blockIdx.x;
    const float4* xp = reinterpret_cast<const float4*>(x + (size_t)bc * VNNN);
    float s = 0.f, ss = 0.f;
    for (int i = threadIdx.x; i < VNNN / 4; i += blockDim.x) {
        float4 v = xp[i];
        s  += v.x + v.y + v.z + v.w;
        ss += v.x*v.x + v.y*v.y + v.z*v.z + v.w*v.w;
    }
    __shared__ float sh_s[8], sh_ss[8];
    #pragma unroll
    for (int o = 16; o; o >>= 1) {
        s  += __shfl_down_sync(0xffffffffu, s, o);
        ss += __shfl_down_sync(0xffffffffu, ss, o);
    }
    int w = threadIdx.x >> 5, l = threadIdx.x & 31;
    if (l == 0) { sh_s[w] = s; sh_ss[w] = ss; }
    __syncthreads();
    if (w == 0) {
        s  = (l < 8) ? sh_s[l]  : 0.f;
        ss = (l < 8) ? sh_ss[l] : 0.f;
        #pragma unroll
        for (int o = 4; o; o >>= 1) {
            s  += __shfl_down_sync(0xffffffffu, s, o);
            ss += __shfl_down_sync(0xffffffffu, ss, o);
        }
        if (l == 0) {
            float mu  = s / (float)VNNN;
            float var = ss / (float)VNNN - mu * mu;
            g_mu[bc] = mu; g_rsig[bc] = rsqrtf(var + SP_EPS);
        }
    }
}

// ---------------------------------------------------------------------------
// transpose x -> padded channel-last bf16 hi/lo
// ---------------------------------------------------------------------------
__global__ __launch_bounds__(256)
void xpose_kernel(const float* __restrict__ x) {
    int pz = blockIdx.x, b = blockIdx.y;
    for (int c = threadIdx.x; c < PDD; c += 256) {
        int py = c / PD, px = c - py * PD;
        size_t lin = (size_t)XOFF + (size_t)b*PDDD + (size_t)pz*PDD + py*PD + px;
        uint4* dh = (uint4*)(g_xp_hi + lin * 32);
        uint4* dl = (uint4*)(g_xp_lo + lin * 32);
        if (pz >= 1 && pz <= 48 && py >= 1 && py <= 48 && px >= 1 && px <= 48) {
            const float* xb = x + (size_t)b*32*VNNN + (size_t)(pz-1)*VNN + (py-1)*VN + (px-1);
            u32 ph[16], pl[16];
            #pragma unroll
            for (int q = 0; q < 16; q++) {
                float v0 = xb[(size_t)(2*q)   * VNNN];
                float v1 = xb[(size_t)(2*q+1) * VNNN];
                __nv_bfloat16 h0 = __float2bfloat16(v0);
                __nv_bfloat16 l0 = __float2bfloat16(v0 - __bfloat162float(h0));
                __nv_bfloat16 h1 = __float2bfloat16(v1);
                __nv_bfloat16 l1 = __float2bfloat16(v1 - __bfloat162float(h1));
                ph[q] = packbf(h0, h1); pl[q] = packbf(l0, l1);
            }
            #pragma unroll
            for (int i = 0; i < 4; i++) { dh[i] = ((uint4*)ph)[i]; dl[i] = ((uint4*)pl)[i]; }
        } else {
            uint4 z = make_uint4(0,0,0,0);
            #pragma unroll
            for (int i = 0; i < 4; i++) { dh[i] = z; dl[i] = z; }
        }
    }
}

__global__ __launch_bounds__(256)
void zhalo_kernel() {
    int pz = blockIdx.x, b = blockIdx.y;
    bool ze = (pz == 0 || pz == 49);
    for (int c = threadIdx.x; c < PDD; c += 256) {
        int py = c / PD, px = c - py * PD;
        if (ze || py == 0 || py == 49 || px == 0 || px == 49) {
            size_t lin = (size_t)XOFF + (size_t)b*PDDD + (size_t)pz*PDD + py*PD + px;
            uint4 z = make_uint4(0,0,0,0);
            uint4* dh = (uint4*)(g_a_hi + lin * 64);
            uint4* dl = (uint4*)(g_a_lo + lin * 64);
            #pragma unroll
            for (int i = 0; i < 8; i++) { dh[i] = z; dl[i] = z; }
        }
    }
}

// ---------------------------------------------------------------------------
// Pre-swizzled B tiles
// ---------------------------------------------------------------------------
__global__ void prepb1_kernel(const float* __restrict__ Ws) {
    int tap = blockIdx.x, cls = blockIdx.y;
    __nv_bfloat16* o0 = g_w1 + ((size_t)(cls*27 + tap)*2 + 0) * 4096;
    __nv_bfloat16* o1 = o0 + 4096;
    for (int i = threadIdx.x; i < 4096; i += 256) {
        int n = i >> 6, k = i & 63, ic = k & 31;
        float w = Ws[((size_t)(cls*64 + n)*32 + ic)*27 + tap];
        __nv_bfloat16 h = __float2bfloat16(w);
        __nv_bfloat16 l = __float2bfloat16(w - __bfloat162float(h));
        u32 sw = sw128((u32)(n*128 + k*2));
        o0[sw >> 1] = h; o1[sw >> 1] = l;
    }
}
__global__ void prepb2_kernel(const float* __restrict__ Wg, const float* __restrict__ Wb) {
    int tap = blockIdx.x, cls = blockIdx.y;
    __nv_bfloat16* o0 = g_w2 + ((size_t)(cls*27 + tap)*2 + 0) * 4096;
    __nv_bfloat16* o1 = o0 + 4096;
    for (int i = threadIdx.x; i < 4096; i += 256) {
        int n = i >> 6, k = i & 63;
        float w = (n < 32) ? Wg[((size_t)(cls*32 + n)*64 + k)*27 + tap]
                           : Wb[((size_t)(cls*32 + (n-32))*64 + k)*27 + tap];
        __nv_bfloat16 h = __float2bfloat16(w);
        __nv_bfloat16 l = __float2bfloat16(w - __bfloat162float(h));
        u32 sw = sw128((u32)(n*128 + k*2));
        o0[sw >> 1] = h; o1[sw >> 1] = l;
    }
}

// ---------------------------------------------------------------------------
// conv1: 32->64 ch. grid (10, 48, 8), 256 thr (8 warps 4m x 2n), occ 2.
// A single-buffered (360 rows x 128B), B double-buffered 16KB.
// ---------------------------------------------------------------------------
#define ASTG (AROWS * 128)
#define C1_DSMEM (ASTG + 2*16384)
__global__ __launch_bounds__(256, 2)
void conv1_kernel(const int* __restrict__ ycls, const float* __restrict__ bsh) {
    extern __shared__ char dsm[];
    __shared__ float s_bias[64];

    int tile = blockIdx.x, pz = blockIdx.y + 1, b = blockIdx.z;
    int cls = ycls[b];
    int tid = threadIdx.x, wid = tid >> 5, lane = tid & 31;
    u32 base = (smem_u32(dsm) + 127) & ~127u;
    if (tid < 64) s_bias[tid] = bsh[cls*64 + tid];
    __syncthreads();

    int q0 = tile * MT;
    size_t brow = (size_t)XOFF + (size_t)b*PDDD + (size_t)pz*PDD + q0;

    auto copyA = [&](int kd) {
        size_t blk = brow + (size_t)(kd - 1) * PDD - 51;
        for (int i = tid; i < AROWS * 8; i += 256) {
            int r = i >> 3, j = i & 7;
            u32 dst = base + sw128((u32)(r*128 + j*16));
            const char* src = (j < 4)
                ? (const char*)(g_xp_hi + (blk + r) * 32) + j*16
                : (const char*)(g_xp_lo + (blk + r) * 32) + (j-4)*16;
            cp16f(dst, src);
        }
    };
    auto copyB = [&](int t, int s) {
        u32 Bs = base + ASTG + (u32)s * 16384;
        const char* bsrc = (const char*)(g_w1 + ((size_t)(cls*27 + t) * 2) * 4096);
        for (int i = tid; i < 1024; i += 256) cp16f(Bs + i*16, bsrc + i*16);
    };

    float acc[4][4][4];
    #pragma unroll
    for (int i = 0; i < 4; i++)
        #pragma unroll
        for (int j = 0; j < 4; j++)
            #pragma unroll
            for (int q = 0; q < 4; q++) acc[i][j][q] = 0.f;

    int arow = (wid >> 1) * 64;
    int nslot = wid & 1;
    int lr = lane & 15, lc = lane >> 4;

    copyA(0); copyB(0, 0); cp_commit();
    for (int t = 0; t < 27; t++) {
        int kd = t / 9, kh = (t % 9) / 3, kw = t % 3;
        cp_wait0();
        __syncthreads();
        int nt = t + 1;
        if (nt < 27 && nt % 9 != 0) { copyB(nt, nt & 1); cp_commit(); }
        u32 Bs = base + ASTG + (u32)(t & 1) * 16384;
        int rowoff = kh * 50 + kw;
        #pragma unroll
        for (int ks = 0; ks < 4; ks++) {
            u32 a[4][4];
            #pragma unroll
            for (int i = 0; i < 4; i++)
                ldsm4(a[i], base + sw128((u32)((arow + 16*i + lr + rowoff)*128 + ks*32 + lc*16)));
            #pragma unroll
            for (int tm = 0; tm < 2; tm++) {
                u32 Bt = Bs + (u32)tm * 8192;
                #pragma unroll
                for (int j = 0; j < 2; j++) {
                    u32 bb[4];
                    ldsm4(bb, Bt + sw128((u32)((nslot*32 + j*16 + lr)*128 + ks*32 + lc*16)));
                    #pragma unroll
                    for (int i = 0; i < 4; i++) {
                        mma16816(acc[i][2*j],   a[i], bb[0], bb[2]);
                        mma16816(acc[i][2*j+1], a[i], bb[1], bb[3]);
                    }
                }
            }
        }
        if (nt < 27 && nt % 9 == 0) {
            __syncthreads();
            copyA(nt / 9); copyB(nt, nt & 1); cp_commit();
        }
    }

    // epilogue: bias + relu -> g_a
    int qr = lane >> 2, qc = (lane & 3) * 2;
    #pragma unroll
    for (int i = 0; i < 4; i++) {
        #pragma unroll
        for (int rr = 0; rr < 2; rr++) {
            int m = arow + 16*i + 8*rr + qr;
            if (m >= MT) continue;
            int q = q0 + m;
            int py = q / 50, px = q - py * 50;
            if (py < 1 || py > 48 || px < 1 || px > 48) continue;
            size_t lin = (size_t)XOFF + (size_t)b*PDDD + (size_t)pz*PDD + q;
            #pragma unroll
            for (int jj = 0; jj < 4; jj++) {
                int ch = nslot*32 + jj*8 + qc;
                float v0 = fmaxf(acc[i][jj][rr*2 + 0] + s_bias[ch],     0.f);
                float v1 = fmaxf(acc[i][jj][rr*2 + 1] + s_bias[ch + 1], 0.f);
                __nv_bfloat16 h0 = __float2bfloat16(v0);
                __nv_bfloat16 l0 = __float2bfloat16(v0 - __bfloat162float(h0));
                __nv_bfloat16 h1 = __float2bfloat16(v1);
                __nv_bfloat16 l1 = __float2bfloat16(v1 - __bfloat162float(h1));
                *(u32*)(g_a_hi + lin*64 + ch) = packbf(h0, h1);
                *(u32*)(g_a_lo + lin*64 + ch) = packbf(l0, l1);
            }
        }
    }
}

// ---------------------------------------------------------------------------
// conv2: 64->64 (gamma|beta) + InstanceNorm. A(hi+lo) single, B single.
// 256 thr (8 warps 4m x 2n), occ 2. smem-exchange epilogue.
// ---------------------------------------------------------------------------
#define C2_DSMEM (2*ASTG + 16384)
__global__ __launch_bounds__(256, 2)
void conv2_kernel(const float* __restrict__ x,
                  const float* __restrict__ bg, const float* __restrict__ bb_,
                  const int* __restrict__ ycls, float* __restrict__ out) {
    extern __shared__ char dsm[];
    __shared__ float s_mu[32], s_rs[32], s_bg[32], s_bb[32];

    int tile = blockIdx.x, pz = blockIdx.y + 1, b = blockIdx.z;
    int cls = ycls[b];
    int tid = threadIdx.x, wid = tid >> 5, lane = tid & 31;
    u32 base = (smem_u32(dsm) + 127) & ~127u;
    if (tid < 32) {
        s_mu[tid] = g_mu[b*32 + tid];
        s_rs[tid] = g_rsig[b*32 + tid];
        s_bg[tid] = bg[cls*32 + tid];
        s_bb[tid] = bb_[cls*32 + tid];
    }
    __syncthreads();

    int q0 = tile * MT;
    size_t brow = (size_t)XOFF + (size_t)b*PDDD + (size_t)pz*PDD + q0;
    u32 AH = base, AL = base + ASTG, Bs = base + 2*ASTG;

    auto copyA = [&](int kd) {
        size_t blk = brow + (size_t)(kd - 1) * PDD - 51;
        for (int i = tid; i < AROWS * 8; i += 256) {
            int r = i >> 3, j = i & 7;
            u32 sw = sw128((u32)(r*128 + j*16));
            cp16f(AH + sw, (const char*)(g_a_hi + (blk + r) * 64) + j*16);
            cp16f(AL + sw, (const char*)(g_a_lo + (blk + r) * 64) + j*16);
        }
    };
    auto copyB = [&](int t) {
        const char* bsrc = (const char*)(g_w2 + ((size_t)(cls*27 + t) * 2) * 4096);
        for (int i = tid; i < 1024; i += 256) cp16f(Bs + i*16, bsrc + i*16);
    };

    float acc[4][4][4];
    #pragma unroll
    for (int i = 0; i < 4; i++)
        #pragma unroll
        for (int j = 0; j < 4; j++)
            #pragma unroll
            for (int q = 0; q < 4; q++) acc[i][j][q] = 0.f;

    int arow = (wid >> 1) * 64;
    int nslot = wid & 1;
    int lr = lane & 15, lc = lane >> 4;

    copyA(0); copyB(0); cp_commit();
    for (int t = 0; t < 27; t++) {
        int kd = t / 9, kh = (t % 9) / 3, kw = t % 3;
        cp_wait0();
        __syncthreads();
        int rowoff = kh * 50 + kw;
        #pragma unroll
        for (int ks = 0; ks < 4; ks++) {
            u32 aH[4][4], aL[4][4];
            #pragma unroll
            for (int i = 0; i < 4; i++) {
                u32 sw = sw128((u32)((arow + 16*i + lr + rowoff)*128 + ks*32 + lc*16));
                ldsm4(aH[i], AH + sw);
                ldsm4(aL[i], AL + sw);
            }
            #pragma unroll
            for (int tm = 0; tm < 2; tm++) {
                u32 Bt = Bs + (u32)tm * 8192;
                #pragma unroll
                for (int j = 0; j < 2; j++) {
                    u32 bb[4];
                    ldsm4(bb, Bt + sw128((u32)((nslot*32 + j*16 + lr)*128 + ks*32 + lc*16)));
                    #pragma unroll
                    for (int i = 0; i < 4; i++) {
                        mma16816(acc[i][2*j],   aH[i], bb[0], bb[2]);
                        mma16816(acc[i][2*j+1], aH[i], bb[1], bb[3]);
                    }
                    if (tm == 0) {
                        #pragma unroll
                        for (int i = 0; i < 4; i++) {
                            mma16816(acc[i][2*j],   aL[i], bb[0], bb[2]);
                            mma16816(acc[i][2*j+1], aL[i], bb[1], bb[3]);
                        }
                    }
                }
            }
        }
        int nt = t + 1;
        if (nt < 27) {
            __syncthreads();
            copyB(nt);
            if (nt % 9 == 0) copyA(nt / 9);
            cp_commit();
        }
    }

    // ---------- exchange epilogue ----------
    __syncthreads();
    float* sg = (float*)(dsm + (base - smem_u32(dsm)));
    float* sb = sg + 256 * 33;

    int qr = lane >> 2, qc = (lane & 3) * 2;
    #pragma unroll
    for (int i = 0; i < 4; i++) {
        #pragma unroll
        for (int rr = 0; rr < 2; rr++) {
            int m = arow + 16*i + 8*rr + qr;
            #pragma unroll
            for (int jj = 0; jj < 4; jj++) {
                int n = nslot*32 + jj*8 + qc;
                float v0 = acc[i][jj][rr*2 + 0];
                float v1 = acc[i][jj][rr*2 + 1];
                if (n < 32) { sg[m*33 + n] = v0; sg[m*33 + n + 1] = v1; }
                else        { sb[m*33 + n - 32] = v0; sb[m*33 + n - 31] = v1; }
            }
        }
    }
    __syncthreads();

    if (tid < MT) {
        int q = q0 + tid;
        int py = q / 50, px = q - py * 50;
        if (py >= 1 && py <= 48 && px >= 1 && px <= 48) {
            size_t sidx = (size_t)b*32*VNNN + (size_t)(pz-1)*VNN + (py-1)*VN + (px-1);
            #pragma unroll 8
            for (int ch = 0; ch < 32; ch++) {
                float gm = sg[tid*33 + ch] + s_bg[ch];
                float bt = sb[tid*33 + ch] + s_bb[ch];
                float xv = x[sidx + (size_t)ch * VNNN];
                out[sidx + (size_t)ch * VNNN] =
                    (xv - s_mu[ch]) * s_rs[ch] * (1.f + gm) + bt;
            }
        }
    }
}

// ---------------------------------------------------------------------------
extern "C" void kernel_launch(void* const* d_in, const int* in_sizes, int n_in,
                              void* d_out, int out_size) {
    const float* x       = (const float*)d_in[0];
    const int*   y       = (const int*)d_in[1];
    const float* Wshared = (const float*)d_in[2];
    const float* bshared = (const float*)d_in[3];
    const float* Wgamma  = (const float*)d_in[4];
    const float* bgamma  = (const float*)d_in[5];
    const float* Wbeta   = (const float*)d_in[6];
    const float* bbeta   = (const float*)d_in[7];
    float* out = (float*)d_out;

    cudaFuncSetAttribute(conv1_kernel, cudaFuncAttributeMaxDynamicSharedMemorySize, C1_DSMEM);
    cudaFuncSetAttribute(conv2_kernel, cudaFuncAttributeMaxDynamicSharedMemorySize, C2_DSMEM);

    stats_kernel<<<NB * 32, 256>>>(x);
    xpose_kernel<<<dim3(PD, NB), 256>>>(x);
    zhalo_kernel<<<dim3(PD, NB), 256>>>();
    prepb1_kernel<<<dim3(27, 4), 256>>>(Wshared);
    prepb2_kernel<<<dim3(27, 4), 256>>>(Wgamma, Wbeta);

    conv1_kernel<<<dim3(NTILE, 48, NB), 256, C1_DSMEM>>>(y, bshared);
    conv2_kernel<<<dim3(NTILE, 48, NB), 256, C2_DSMEM>>>(x, bgamma, bbeta, y, out);
}

// round 9
// speedup vs baseline: 3.7536x; 1.3441x over previous
#include <cuda_runtime.h>
#include <cuda_bf16.h>
#include <cstdint>

typedef unsigned int u32;
typedef unsigned long long u64;

#define VN 48
#define VNN 2304
#define VNNN 110592
#define NB 8
#define SP_EPS 1e-5f
#define PD 50
#define PDD 2500
#define PDDD 125000
#define XOFF 128

// conv1 tiling
#define NTILE1 10
#define MT1 250
#define AROWS1 360
// conv2 tiling
#define NTILE2 5
#define MT2 500
#define AROWS2 620
#define ASTRIDE2 272

// ---------------- device scratch ----------------
__device__ __nv_bfloat16 g_xp_hi[((size_t)NB * PDDD + 2 * XOFF) * 32];
__device__ __nv_bfloat16 g_xp_lo[((size_t)NB * PDDD + 2 * XOFF) * 32];
__device__ float         g_af  [((size_t)NB * PDDD + 2 * XOFF) * 64];
__device__ __nv_bfloat16 g_w1[4 * 27 * 2 * 4096];
__device__ float         g_w2f[4 * 27 * 4096];
__device__ float g_mu[NB * 32];
__device__ float g_rsig[NB * 32];

// ---------------- helpers ----------------
__device__ __forceinline__ u32 smem_u32(const void* p) {
    u32 a; asm("{ .reg .u64 t; cvta.to.shared.u64 t, %1; cvt.u32.u64 %0, t; }"
               : "=r"(a) : "l"(p));
    return a;
}
__device__ __forceinline__ void cp16f(u32 dst, const void* src) {
    asm volatile("cp.async.ca.shared.global [%0], [%1], 16;" :: "r"(dst), "l"(src));
}
__device__ __forceinline__ void cp_commit() { asm volatile("cp.async.commit_group;"); }
__device__ __forceinline__ void cp_wait0()  { asm volatile("cp.async.wait_group 0;" ::: "memory"); }
__device__ __forceinline__ u32 packbf(__nv_bfloat16 a, __nv_bfloat16 b) {
    __nv_bfloat162 p(a, b); return *reinterpret_cast<u32*>(&p);
}
__device__ __forceinline__ u32 sw128(u32 off) { return off ^ ((off >> 3) & 0x70); }
__device__ __forceinline__ u32 tf32r(float v) {
    u32 r; asm("cvt.rna.tf32.f32 %0, %1;" : "=r"(r) : "f"(v)); return r;
}
__device__ __forceinline__ void ldsm4(u32* r, u32 addr) {
    asm volatile("ldmatrix.sync.aligned.m8n8.x4.shared.b16 {%0,%1,%2,%3}, [%4];"
        : "=r"(r[0]), "=r"(r[1]), "=r"(r[2]), "=r"(r[3]) : "r"(addr));
}
__device__ __forceinline__ void lds32(u32& r, u32 addr) {
    asm volatile("ld.shared.b32 %0, [%1];" : "=r"(r) : "r"(addr));
}
__device__ __forceinline__ void lds64(u32& r0, u32& r1, u32 addr) {
    asm volatile("ld.shared.v2.b32 {%0,%1}, [%2];" : "=r"(r0), "=r"(r1) : "r"(addr));
}
__device__ __forceinline__ void mma16816(float* d, const u32* a, u32 b0, u32 b1) {
    asm volatile("mma.sync.aligned.m16n8k16.row.col.f32.bf16.bf16.f32 "
        "{%0,%1,%2,%3}, {%4,%5,%6,%7}, {%8,%9}, {%0,%1,%2,%3};"
        : "+f"(d[0]), "+f"(d[1]), "+f"(d[2]), "+f"(d[3])
        : "r"(a[0]), "r"(a[1]), "r"(a[2]), "r"(a[3]), "r"(b0), "r"(b1));
}
__device__ __forceinline__ void mmatf32(float* d, const u32* a, u32 b0, u32 b1) {
    asm volatile("mma.sync.aligned.m16n8k8.row.col.f32.tf32.tf32.f32 "
        "{%0,%1,%2,%3}, {%4,%5,%6,%7}, {%8,%9}, {%0,%1,%2,%3};"
        : "+f"(d[0]), "+f"(d[1]), "+f"(d[2]), "+f"(d[3])
        : "r"(a[0]), "r"(a[1]), "r"(a[2]), "r"(a[3]), "r"(b0), "r"(b1));
}

// ---------------------------------------------------------------------------
// stats
// ---------------------------------------------------------------------------
__global__ void stats_kernel(const float* __restrict__ x) {
    int bc = blockIdx.x;
    const float4* xp = reinterpret_cast<const float4*>(x + (size_t)bc * VNNN);
    float s = 0.f, ss = 0.f;
    for (int i = threadIdx.x; i < VNNN / 4; i += blockDim.x) {
        float4 v = xp[i];
        s  += v.x + v.y + v.z + v.w;
        ss += v.x*v.x + v.y*v.y + v.z*v.z + v.w*v.w;
    }
    __shared__ float sh_s[8], sh_ss[8];
    #pragma unroll
    for (int o = 16; o; o >>= 1) {
        s  += __shfl_down_sync(0xffffffffu, s, o);
        ss += __shfl_down_sync(0xffffffffu, ss, o);
    }
    int w = threadIdx.x >> 5, l = threadIdx.x & 31;
    if (l == 0) { sh_s[w] = s; sh_ss[w] = ss; }
    __syncthreads();
    if (w == 0) {
        s  = (l < 8) ? sh_s[l]  : 0.f;
        ss = (l < 8) ? sh_ss[l] : 0.f;
        #pragma unroll
        for (int o = 4; o; o >>= 1) {
            s  += __shfl_down_sync(0xffffffffu, s, o);
            ss += __shfl_down_sync(0xffffffffu, ss, o);
        }
        if (l == 0) {
            float mu  = s / (float)VNNN;
            float var = ss / (float)VNNN - mu * mu;
            g_mu[bc] = mu; g_rsig[bc] = rsqrtf(var + SP_EPS);
        }
    }
}

// ---------------------------------------------------------------------------
// transpose x -> padded channel-last bf16 hi/lo
// ---------------------------------------------------------------------------
__global__ __launch_bounds__(256)
void xpose_kernel(const float* __restrict__ x) {
    int pz = blockIdx.x, b = blockIdx.y;
    for (int c = threadIdx.x; c < PDD; c += 256) {
        int py = c / PD, px = c - py * PD;
        size_t lin = (size_t)XOFF + (size_t)b*PDDD + (size_t)pz*PDD + py*PD + px;
        uint4* dh = (uint4*)(g_xp_hi + lin * 32);
        uint4* dl = (uint4*)(g_xp_lo + lin * 32);
        if (pz >= 1 && pz <= 48 && py >= 1 && py <= 48 && px >= 1 && px <= 48) {
            const float* xb = x + (size_t)b*32*VNNN + (size_t)(pz-1)*VNN + (py-1)*VN + (px-1);
            u32 ph[16], pl[16];
            #pragma unroll
            for (int q = 0; q < 16; q++) {
                float v0 = xb[(size_t)(2*q)   * VNNN];
                float v1 = xb[(size_t)(2*q+1) * VNNN];
                __nv_bfloat16 h0 = __float2bfloat16(v0);
                __nv_bfloat16 l0 = __float2bfloat16(v0 - __bfloat162float(h0));
                __nv_bfloat16 h1 = __float2bfloat16(v1);
                __nv_bfloat16 l1 = __float2bfloat16(v1 - __bfloat162float(h1));
                ph[q] = packbf(h0, h1); pl[q] = packbf(l0, l1);
            }
            #pragma unroll
            for (int i = 0; i < 4; i++) { dh[i] = ((uint4*)ph)[i]; dl[i] = ((uint4*)pl)[i]; }
        } else {
            uint4 z = make_uint4(0,0,0,0);
            #pragma unroll
            for (int i = 0; i < 4; i++) { dh[i] = z; dl[i] = z; }
        }
    }
}

// zero the halo cells of g_af
__global__ __launch_bounds__(256)
void zhalo_kernel() {
    int pz = blockIdx.x, b = blockIdx.y;
    bool ze = (pz == 0 || pz == 49);
    for (int c = threadIdx.x; c < PDD; c += 256) {
        int py = c / PD, px = c - py * PD;
        if (ze || py == 0 || py == 49 || px == 0 || px == 49) {
            size_t lin = (size_t)XOFF + (size_t)b*PDDD + (size_t)pz*PDD + py*PD + px;
            float4 z = make_float4(0.f,0.f,0.f,0.f);
            float4* d = (float4*)(g_af + lin * 64);
            #pragma unroll
            for (int i = 0; i < 16; i++) d[i] = z;
        }
    }
}

// ---------------------------------------------------------------------------
// Pre-arranged B tiles
// ---------------------------------------------------------------------------
__global__ void prepb1_kernel(const float* __restrict__ Ws) {
    int tap = blockIdx.x, cls = blockIdx.y;
    __nv_bfloat16* o0 = g_w1 + ((size_t)(cls*27 + tap)*2 + 0) * 4096;
    __nv_bfloat16* o1 = o0 + 4096;
    for (int i = threadIdx.x; i < 4096; i += 256) {
        int n = i >> 6, k = i & 63, ic = k & 31;
        float w = Ws[((size_t)(cls*64 + n)*32 + ic)*27 + tap];
        __nv_bfloat16 h = __float2bfloat16(w);
        __nv_bfloat16 l = __float2bfloat16(w - __bfloat162float(h));
        u32 sw = sw128((u32)(n*128 + k*2));
        o0[sw >> 1] = h; o1[sw >> 1] = l;
    }
}
// conv2 tf32 tiles, lane-major pair layout for m16n8k8 B frags
__global__ void prepb2_kernel(const float* __restrict__ Wg, const float* __restrict__ Wb) {
    int tap = blockIdx.x, cls = blockIdx.y;
    float* o = g_w2f + (size_t)(cls*27 + tap) * 4096;
    for (int i = threadIdx.x; i < 4096; i += 256) {
        int n = i >> 6, k = i & 63;
        float w = (n < 32) ? Wg[((size_t)(cls*32 + n)*64 + k)*27 + tap]
                           : Wb[((size_t)(cls*32 + (n-32))*64 + k)*27 + tap];
        u32 t = tf32r(w);
        int ks = k >> 3, kc = k & 7, c = kc & 3, p = kc >> 2;
        int nc = n >> 3, g = n & 7;
        int lane = g*4 + c;
        int slot = ((ks*8 + nc)*32 + lane)*2 + p;
        o[slot] = __uint_as_float(t);
    }
}

// ---------------------------------------------------------------------------
// conv1: 32->64 ch, bf16 3-term split. 256 thr (4m x 2n), occ 2.
// ---------------------------------------------------------------------------
#define ASTG1 (AROWS1 * 128)
#define C1_DSMEM (ASTG1 + 2*16384)
__global__ __launch_bounds__(256, 2)
void conv1_kernel(const int* __restrict__ ycls, const float* __restrict__ bsh) {
    extern __shared__ char dsm[];
    __shared__ float s_bias[64];

    int tile = blockIdx.x, pz = blockIdx.y + 1, b = blockIdx.z;
    int cls = ycls[b];
    int tid = threadIdx.x, wid = tid >> 5, lane = tid & 31;
    u32 base = (smem_u32(dsm) + 127) & ~127u;
    if (tid < 64) s_bias[tid] = bsh[cls*64 + tid];
    __syncthreads();

    int q0 = tile * MT1;
    size_t brow = (size_t)XOFF + (size_t)b*PDDD + (size_t)pz*PDD + q0;

    auto copyA = [&](int kd) {
        size_t blk = brow + (size_t)(kd - 1) * PDD - 51;
        for (int i = tid; i < AROWS1 * 8; i += 256) {
            int r = i >> 3, j = i & 7;
            u32 dst = base + sw128((u32)(r*128 + j*16));
            const char* src = (j < 4)
                ? (const char*)(g_xp_hi + (blk + r) * 32) + j*16
                : (const char*)(g_xp_lo + (blk + r) * 32) + (j-4)*16;
            cp16f(dst, src);
        }
    };
    auto copyB = [&](int t, int s) {
        u32 Bs = base + ASTG1 + (u32)s * 16384;
        const char* bsrc = (const char*)(g_w1 + ((size_t)(cls*27 + t) * 2) * 4096);
        for (int i = tid; i < 1024; i += 256) cp16f(Bs + i*16, bsrc + i*16);
    };

    float acc[4][4][4];
    #pragma unroll
    for (int i = 0; i < 4; i++)
        #pragma unroll
        for (int j = 0; j < 4; j++)
            #pragma unroll
            for (int q = 0; q < 4; q++) acc[i][j][q] = 0.f;

    int arow = (wid >> 1) * 64;
    int nslot = wid & 1;
    int lr = lane & 15, lc = lane >> 4;

    copyA(0); copyB(0, 0); cp_commit();
    for (int t = 0; t < 27; t++) {
        int kd = t / 9, kh = (t % 9) / 3, kw = t % 3;
        cp_wait0();
        __syncthreads();
        int nt = t + 1;
        if (nt < 27 && nt % 9 != 0) { copyB(nt, nt & 1); cp_commit(); }
        u32 Bs = base + ASTG1 + (u32)(t & 1) * 16384;
        int rowoff = kh * 50 + kw;
        #pragma unroll
        for (int ks = 0; ks < 4; ks++) {
            u32 a[4][4];
            #pragma unroll
            for (int i = 0; i < 4; i++)
                ldsm4(a[i], base + sw128((u32)((arow + 16*i + lr + rowoff)*128 + ks*32 + lc*16)));
            #pragma unroll
            for (int tm = 0; tm < 2; tm++) {
                if (tm == 1 && ks >= 2) continue;   // drop al*wl: lo-term only k<32
                u32 Bt = Bs + (u32)tm * 8192;
                #pragma unroll
                for (int j = 0; j < 2; j++) {
                    u32 bb[4];
                    ldsm4(bb, Bt + sw128((u32)((nslot*32 + j*16 + lr)*128 + ks*32 + lc*16)));
                    #pragma unroll
                    for (int i = 0; i < 4; i++) {
                        mma16816(acc[i][2*j],   a[i], bb[0], bb[2]);
                        mma16816(acc[i][2*j+1], a[i], bb[1], bb[3]);
                    }
                }
            }
        }
        if (nt < 27 && nt % 9 == 0) {
            __syncthreads();
            copyA(nt / 9); copyB(nt, nt & 1); cp_commit();
        }
    }

    // epilogue: bias + relu -> g_af (tf32-rounded fp32)
    int qr = lane >> 2, qc = (lane & 3) * 2;
    #pragma unroll
    for (int i = 0; i < 4; i++) {
        #pragma unroll
        for (int rr = 0; rr < 2; rr++) {
            int m = arow + 16*i + 8*rr + qr;
            if (m >= MT1) continue;
            int q = q0 + m;
            int py = q / 50, px = q - py * 50;
            if (py < 1 || py > 48 || px < 1 || px > 48) continue;
            size_t lin = (size_t)XOFF + (size_t)b*PDDD + (size_t)pz*PDD + q;
            #pragma unroll
            for (int jj = 0; jj < 4; jj++) {
                int ch = nslot*32 + jj*8 + qc;
                float v0 = fmaxf(acc[i][jj][rr*2 + 0] + s_bias[ch],     0.f);
                float v1 = fmaxf(acc[i][jj][rr*2 + 1] + s_bias[ch + 1], 0.f);
                float2 st = make_float2(__uint_as_float(tf32r(v0)),
                                        __uint_as_float(tf32r(v1)));
                *(float2*)(g_af + lin*64 + ch) = st;
            }
        }
    }
}

// ---------------------------------------------------------------------------
// conv2: tf32 single-pass 64->64 (gamma|beta) + InstanceNorm.
// 512 thr (8m x 2n), occ 1. A single (620 rows x 272B), B dbuf 16KB.
// ---------------------------------------------------------------------------
#define ASTG2 (AROWS2 * ASTRIDE2)
#define C2_DSMEM (ASTG2 + 2*16384)
__global__ __launch_bounds__(512, 1)
void conv2_kernel(const float* __restrict__ x,
                  const float* __restrict__ bg, const float* __restrict__ bb_,
                  const int* __restrict__ ycls, float* __restrict__ out) {
    extern __shared__ char dsm[];
    __shared__ float s_mu[32], s_rs[32], s_bg[32], s_bb[32];

    int tile = blockIdx.x, pz = blockIdx.y + 1, b = blockIdx.z;
    int cls = ycls[b];
    int tid = threadIdx.x, wid = tid >> 5, lane = tid & 31;
    u32 base = (smem_u32(dsm) + 127) & ~127u;
    if (tid < 32) {
        s_mu[tid] = g_mu[b*32 + tid];
        s_rs[tid] = g_rsig[b*32 + tid];
        s_bg[tid] = bg[cls*32 + tid];
        s_bb[tid] = bb_[cls*32 + tid];
    }
    __syncthreads();

    int q0 = tile * MT2;
    size_t brow = (size_t)XOFF + (size_t)b*PDDD + (size_t)pz*PDD + q0;
    u32 AH = base;

    auto copyA = [&](int kd) {
        size_t blk = brow + (size_t)(kd - 1) * PDD - 51;
        for (int i = tid; i < AROWS2 * 16; i += 512) {
            int r = i >> 4, j = i & 15;
            cp16f(AH + (u32)r*ASTRIDE2 + (u32)j*16,
                  (const char*)(g_af + (blk + r) * 64) + j*16);
        }
    };
    auto copyB = [&](int t, int s) {
        u32 Bs = base + ASTG2 + (u32)s * 16384;
        const char* bsrc = (const char*)(g_w2f + (size_t)(cls*27 + t) * 4096);
        for (int i = tid; i < 1024; i += 512) cp16f(Bs + i*16, bsrc + i*16);
    };

    float acc[4][4][4];
    #pragma unroll
    for (int i = 0; i < 4; i++)
        #pragma unroll
        for (int j = 0; j < 4; j++)
            #pragma unroll
            for (int q = 0; q < 4; q++) acc[i][j][q] = 0.f;

    int arow = (wid >> 1) * 64;
    int nslot = wid & 1;
    int lr4 = lane >> 2, lc4 = lane & 3;

    copyA(0); copyB(0, 0); cp_commit();
    for (int t = 0; t < 27; t++) {
        int kd = t / 9, kh = (t % 9) / 3, kw = t % 3;
        cp_wait0();
        __syncthreads();
        int nt = t + 1;
        if (nt < 27 && nt % 9 != 0) { copyB(nt, nt & 1); cp_commit(); }
        u32 Bs = base + ASTG2 + (u32)(t & 1) * 16384;
        int rowoff = kh * 50 + kw;
        u32 abase[4];
        #pragma unroll
        for (int i = 0; i < 4; i++)
            abase[i] = AH + (u32)(arow + 16*i + lr4 + rowoff) * ASTRIDE2 + (u32)lc4 * 4;
        #pragma unroll
        for (int ks = 0; ks < 8; ks++) {
            u32 a[4][4];
            #pragma unroll
            for (int i = 0; i < 4; i++) {
                lds32(a[i][0], abase[i] + ks*32);
                lds32(a[i][1], abase[i] + 8*ASTRIDE2 + ks*32);
                lds32(a[i][2], abase[i] + ks*32 + 16);
                lds32(a[i][3], abase[i] + 8*ASTRIDE2 + ks*32 + 16);
            }
            u32 bf[4][2];
            #pragma unroll
            for (int nc = 0; nc < 4; nc++)
                lds64(bf[nc][0], bf[nc][1],
                      Bs + (u32)(((ks*8 + nslot*4 + nc)*32 + lane)*8));
            #pragma unroll
            for (int i = 0; i < 4; i++)
                #pragma unroll
                for (int nc = 0; nc < 4; nc++)
                    mmatf32(acc[i][nc], a[i], bf[nc][0], bf[nc][1]);
        }
        if (nt < 27 && nt % 9 == 0) {
            __syncthreads();
            copyA(nt / 9); copyB(nt, nt & 1); cp_commit();
        }
    }

    // ---------- exchange epilogue ----------
    __syncthreads();
    float* sg = (float*)(dsm + (base - smem_u32(dsm)));
    float* sb = sg + 512 * 33;

    int qr = lane >> 2, qc = (lane & 3) * 2;
    #pragma unroll
    for (int i = 0; i < 4; i++) {
        #pragma unroll
        for (int rr = 0; rr < 2; rr++) {
            int m = arow + 16*i + 8*rr + qr;
            #pragma unroll
            for (int nc = 0; nc < 4; nc++) {
                int n = nslot*32 + nc*8 + qc;
                float v0 = acc[i][nc][rr*2 + 0];
                float v1 = acc[i][nc][rr*2 + 1];
                if (n < 32) { sg[m*33 + n] = v0; sg[m*33 + n + 1] = v1; }
                else        { sb[m*33 + n - 32] = v0; sb[m*33 + n - 31] = v1; }
            }
        }
    }
    __syncthreads();

    if (tid < MT2) {
        int q = q0 + tid;
        int py = q / 50, px = q - py * 50;
        if (py >= 1 && py <= 48 && px >= 1 && px <= 48) {
            size_t sidx = (size_t)b*32*VNNN + (size_t)(pz-1)*VNN + (py-1)*VN + (px-1);
            #pragma unroll 8
            for (int ch = 0; ch < 32; ch++) {
                float gm = sg[tid*33 + ch] + s_bg[ch];
                float bt = sb[tid*33 + ch] + s_bb[ch];
                float xv = x[sidx + (size_t)ch * VNNN];
                out[sidx + (size_t)ch * VNNN] =
                    (xv - s_mu[ch]) * s_rs[ch] * (1.f + gm) + bt;
            }
        }
    }
}

// ---------------------------------------------------------------------------
extern "C" void kernel_launch(void* const* d_in, const int* in_sizes, int n_in,
                              void* d_out, int out_size) {
    const float* x       = (const float*)d_in[0];
    const int*   y       = (const int*)d_in[1];
    const float* Wshared = (const float*)d_in[2];
    const float* bshared = (const float*)d_in[3];
    const float* Wgamma  = (const float*)d_in[4];
    const float* bgamma  = (const float*)d_in[5];
    const float* Wbeta   = (const float*)d_in[6];
    const float* bbeta   = (const float*)d_in[7];
    float* out = (float*)d_out;

    cudaFuncSetAttribute(conv1_kernel, cudaFuncAttributeMaxDynamicSharedMemorySize, C1_DSMEM);
    cudaFuncSetAttribute(conv2_kernel, cudaFuncAttributeMaxDynamicSharedMemorySize, C2_DSMEM);

    stats_kernel<<<NB * 32, 256>>>(x);
    xpose_kernel<<<dim3(PD, NB), 256>>>(x);
    zhalo_kernel<<<dim3(PD, NB), 256>>>();
    prepb1_kernel<<<dim3(27, 4), 256>>>(Wshared);
    prepb2_kernel<<<dim3(27, 4), 256>>>(Wgamma, Wbeta);

    conv1_kernel<<<dim3(NTILE1, 48, NB), 256, C1_DSMEM>>>(y, bshared);
    conv2_kernel<<<dim3(NTILE2, 48, NB), 512, C2_DSMEM>>>(x, bgamma, bbeta, y, out);
}

// round 10
// speedup vs baseline: 4.2628x; 1.1357x over previous
#include <cuda_runtime.h>
#include <cuda_bf16.h>
#include <cstdint>

typedef unsigned int u32;
typedef unsigned long long u64;

#define VN 48
#define VNN 2304
#define VNNN 110592
#define NB 8
#define SP_EPS 1e-5f
#define PD 50
#define PDD 2500
#define PDDD 125000
#define XOFF 128

#define NTILE 5
#define MT 500
#define AROWS 620
#define ASTRIDE1 144      // conv1 A row: 32 fp32 = 128B + 16 pad
#define ASTRIDE2 272      // conv2 A row: 64 fp32 = 256B + 16 pad

// ---------------- device scratch ----------------
__device__ float g_xf [((size_t)NB * PDDD + 2 * XOFF) * 32];
__device__ float g_af [((size_t)NB * PDDD + 2 * XOFF) * 64];
__device__ float g_w1f[4 * 27 * 2048];
__device__ float g_w2f[4 * 27 * 4096];
__device__ float g_mu[NB * 32];
__device__ float g_rsig[NB * 32];

// ---------------- helpers ----------------
__device__ __forceinline__ u32 smem_u32(const void* p) {
    u32 a; asm("{ .reg .u64 t; cvta.to.shared.u64 t, %1; cvt.u32.u64 %0, t; }"
               : "=r"(a) : "l"(p));
    return a;
}
__device__ __forceinline__ void cp16f(u32 dst, const void* src) {
    asm volatile("cp.async.ca.shared.global [%0], [%1], 16;" :: "r"(dst), "l"(src));
}
__device__ __forceinline__ void cp_commit() { asm volatile("cp.async.commit_group;"); }
__device__ __forceinline__ void cp_wait0()  { asm volatile("cp.async.wait_group 0;" ::: "memory"); }
__device__ __forceinline__ u32 tf32r(float v) {
    u32 r; asm("cvt.rna.tf32.f32 %0, %1;" : "=r"(r) : "f"(v)); return r;
}
__device__ __forceinline__ void lds32(u32& r, u32 addr) {
    asm volatile("ld.shared.b32 %0, [%1];" : "=r"(r) : "r"(addr));
}
__device__ __forceinline__ void lds64(u32& r0, u32& r1, u32 addr) {
    asm volatile("ld.shared.v2.b32 {%0,%1}, [%2];" : "=r"(r0), "=r"(r1) : "r"(addr));
}
__device__ __forceinline__ void mmatf32(float* d, const u32* a, u32 b0, u32 b1) {
    asm volatile("mma.sync.aligned.m16n8k8.row.col.f32.tf32.tf32.f32 "
        "{%0,%1,%2,%3}, {%4,%5,%6,%7}, {%8,%9}, {%0,%1,%2,%3};"
        : "+f"(d[0]), "+f"(d[1]), "+f"(d[2]), "+f"(d[3])
        : "r"(a[0]), "r"(a[1]), "r"(a[2]), "r"(a[3]), "r"(b0), "r"(b1));
}

// ---------------------------------------------------------------------------
// stats
// ---------------------------------------------------------------------------
__global__ void stats_kernel(const float* __restrict__ x) {
    int bc = blockIdx.x;
    const float4* xp = reinterpret_cast<const float4*>(x + (size_t)bc * VNNN);
    float s = 0.f, ss = 0.f;
    for (int i = threadIdx.x; i < VNNN / 4; i += blockDim.x) {
        float4 v = xp[i];
        s  += v.x + v.y + v.z + v.w;
        ss += v.x*v.x + v.y*v.y + v.z*v.z + v.w*v.w;
    }
    __shared__ float sh_s[8], sh_ss[8];
    #pragma unroll
    for (int o = 16; o; o >>= 1) {
        s  += __shfl_down_sync(0xffffffffu, s, o);
        ss += __shfl_down_sync(0xffffffffu, ss, o);
    }
    int w = threadIdx.x >> 5, l = threadIdx.x & 31;
    if (l == 0) { sh_s[w] = s; sh_ss[w] = ss; }
    __syncthreads();
    if (w == 0) {
        s  = (l < 8) ? sh_s[l]  : 0.f;
        ss = (l < 8) ? sh_ss[l] : 0.f;
        #pragma unroll
        for (int o = 4; o; o >>= 1) {
            s  += __shfl_down_sync(0xffffffffu, s, o);
            ss += __shfl_down_sync(0xffffffffu, ss, o);
        }
        if (l == 0) {
            float mu  = s / (float)VNNN;
            float var = ss / (float)VNNN - mu * mu;
            g_mu[bc] = mu; g_rsig[bc] = rsqrtf(var + SP_EPS);
        }
    }
}

// ---------------------------------------------------------------------------
// transpose x -> padded channel-last fp32 (tf32-rounded), zeros in halo
// ---------------------------------------------------------------------------
__global__ __launch_bounds__(256)
void xpose_kernel(const float* __restrict__ x) {
    int pz = blockIdx.x, b = blockIdx.y;
    for (int c = threadIdx.x; c < PDD; c += 256) {
        int py = c / PD, px = c - py * PD;
        size_t lin = (size_t)XOFF + (size_t)b*PDDD + (size_t)pz*PDD + py*PD + px;
        float4* d = (float4*)(g_xf + lin * 32);
        if (pz >= 1 && pz <= 48 && py >= 1 && py <= 48 && px >= 1 && px <= 48) {
            const float* xb = x + (size_t)b*32*VNNN + (size_t)(pz-1)*VNN + (py-1)*VN + (px-1);
            u32 p[32];
            #pragma unroll
            for (int q = 0; q < 32; q++) p[q] = tf32r(xb[(size_t)q * VNNN]);
            #pragma unroll
            for (int i = 0; i < 8; i++) d[i] = ((float4*)p)[i];
        } else {
            float4 z = make_float4(0.f,0.f,0.f,0.f);
            #pragma unroll
            for (int i = 0; i < 8; i++) d[i] = z;
        }
    }
}

// zero the halo cells of g_af
__global__ __launch_bounds__(256)
void zhalo_kernel() {
    int pz = blockIdx.x, b = blockIdx.y;
    bool ze = (pz == 0 || pz == 49);
    for (int c = threadIdx.x; c < PDD; c += 256) {
        int py = c / PD, px = c - py * PD;
        if (ze || py == 0 || py == 49 || px == 0 || px == 49) {
            size_t lin = (size_t)XOFF + (size_t)b*PDDD + (size_t)pz*PDD + py*PD + px;
            float4 z = make_float4(0.f,0.f,0.f,0.f);
            float4* d = (float4*)(g_af + lin * 64);
            #pragma unroll
            for (int i = 0; i < 16; i++) d[i] = z;
        }
    }
}

// ---------------------------------------------------------------------------
// Pre-arranged tf32 B tiles, lane-major pair layout for m16n8k8 frags
// ---------------------------------------------------------------------------
__global__ void prepb1_kernel(const float* __restrict__ Ws) {
    int tap = blockIdx.x, cls = blockIdx.y;
    float* o = g_w1f + (size_t)(cls*27 + tap) * 2048;
    for (int i = threadIdx.x; i < 2048; i += 256) {
        int n = i >> 5, k = i & 31;
        float w = Ws[((size_t)(cls*64 + n)*32 + k)*27 + tap];
        u32 t = tf32r(w);
        int ks = k >> 3, kc = k & 7, c = kc & 3, p = kc >> 2;
        int nc = n >> 3, g = n & 7;
        int lane = g*4 + c;
        int slot = ((ks*8 + nc)*32 + lane)*2 + p;
        o[slot] = __uint_as_float(t);
    }
}
__global__ void prepb2_kernel(const float* __restrict__ Wg, const float* __restrict__ Wb) {
    int tap = blockIdx.x, cls = blockIdx.y;
    float* o = g_w2f + (size_t)(cls*27 + tap) * 4096;
    for (int i = threadIdx.x; i < 4096; i += 256) {
        int n = i >> 6, k = i & 63;
        float w = (n < 32) ? Wg[((size_t)(cls*32 + n)*64 + k)*27 + tap]
                           : Wb[((size_t)(cls*32 + (n-32))*64 + k)*27 + tap];
        u32 t = tf32r(w);
        int ks = k >> 3, kc = k & 7, c = kc & 3, p = kc >> 2;
        int nc = n >> 3, g = n & 7;
        int lane = g*4 + c;
        int slot = ((ks*8 + nc)*32 + lane)*2 + p;
        o[slot] = __uint_as_float(t);
    }
}

// ---------------------------------------------------------------------------
// conv1: tf32 single-pass 32->64 + bias/relu. 512 thr (8m x 2n).
// A single (620 rows x 144B), B dbuf 8KB.
// ---------------------------------------------------------------------------
#define ASTG1 (AROWS * ASTRIDE1)
#define C1_DSMEM (ASTG1 + 2*8192)
__global__ __launch_bounds__(512, 1)
void conv1_kernel(const int* __restrict__ ycls, const float* __restrict__ bsh) {
    extern __shared__ char dsm[];
    __shared__ float s_bias[64];

    int tile = blockIdx.x, pz = blockIdx.y + 1, b = blockIdx.z;
    int cls = ycls[b];
    int tid = threadIdx.x, wid = tid >> 5, lane = tid & 31;
    u32 base = (smem_u32(dsm) + 127) & ~127u;
    if (tid < 64) s_bias[tid] = bsh[cls*64 + tid];
    __syncthreads();

    int q0 = tile * MT;
    size_t brow = (size_t)XOFF + (size_t)b*PDDD + (size_t)pz*PDD + q0;
    u32 AH = base;

    auto copyA = [&](int kd) {
        size_t blk = brow + (size_t)(kd - 1) * PDD - 51;
        for (int i = tid; i < AROWS * 8; i += 512) {
            int r = i >> 3, j = i & 7;
            cp16f(AH + (u32)r*ASTRIDE1 + (u32)j*16,
                  (const char*)(g_xf + (blk + r) * 32) + j*16);
        }
    };
    auto copyB = [&](int t, int s) {
        u32 Bs = base + ASTG1 + (u32)s * 8192;
        const char* bsrc = (const char*)(g_w1f + (size_t)(cls*27 + t) * 2048);
        for (int i = tid; i < 512; i += 512) cp16f(Bs + i*16, bsrc + i*16);
    };

    float acc[4][4][4];
    #pragma unroll
    for (int i = 0; i < 4; i++)
        #pragma unroll
        for (int j = 0; j < 4; j++)
            #pragma unroll
            for (int q = 0; q < 4; q++) acc[i][j][q] = 0.f;

    int arow = (wid >> 1) * 64;
    int nslot = wid & 1;
    int lr4 = lane >> 2, lc4 = lane & 3;

    copyA(0); copyB(0, 0); cp_commit();
    for (int t = 0; t < 27; t++) {
        int kd = t / 9, kh = (t % 9) / 3, kw = t % 3;
        cp_wait0();
        __syncthreads();
        int nt = t + 1;
        if (nt < 27 && nt % 9 != 0) { copyB(nt, nt & 1); cp_commit(); }
        u32 Bs = base + ASTG1 + (u32)(t & 1) * 8192;
        int rowoff = kh * 50 + kw;
        u32 abase[4];
        #pragma unroll
        for (int i = 0; i < 4; i++)
            abase[i] = AH + (u32)(arow + 16*i + lr4 + rowoff) * ASTRIDE1 + (u32)lc4 * 4;
        #pragma unroll
        for (int ks = 0; ks < 4; ks++) {
            u32 a[4][4];
            #pragma unroll
            for (int i = 0; i < 4; i++) {
                lds32(a[i][0], abase[i] + ks*32);
                lds32(a[i][1], abase[i] + 8*ASTRIDE1 + ks*32);
                lds32(a[i][2], abase[i] + ks*32 + 16);
                lds32(a[i][3], abase[i] + 8*ASTRIDE1 + ks*32 + 16);
            }
            u32 bf[4][2];
            #pragma unroll
            for (int nc = 0; nc < 4; nc++)
                lds64(bf[nc][0], bf[nc][1],
                      Bs + (u32)(((ks*8 + nslot*4 + nc)*32 + lane)*8));
            #pragma unroll
            for (int i = 0; i < 4; i++)
                #pragma unroll
                for (int nc = 0; nc < 4; nc++)
                    mmatf32(acc[i][nc], a[i], bf[nc][0], bf[nc][1]);
        }
        if (nt < 27 && nt % 9 == 0) {
            __syncthreads();
            copyA(nt / 9); copyB(nt, nt & 1); cp_commit();
        }
    }

    // epilogue: bias + relu -> g_af (tf32-rounded fp32, channel-last)
    int qr = lane >> 2, qc = (lane & 3) * 2;
    #pragma unroll
    for (int i = 0; i < 4; i++) {
        #pragma unroll
        for (int rr = 0; rr < 2; rr++) {
            int m = arow + 16*i + 8*rr + qr;
            if (m >= MT) continue;
            int q = q0 + m;
            int py = q / 50, px = q - py * 50;
            if (py < 1 || py > 48 || px < 1 || px > 48) continue;
            size_t lin = (size_t)XOFF + (size_t)b*PDDD + (size_t)pz*PDD + q;
            #pragma unroll
            for (int nc = 0; nc < 4; nc++) {
                int ch = nslot*32 + nc*8 + qc;
                float v0 = fmaxf(acc[i][nc][rr*2 + 0] + s_bias[ch],     0.f);
                float v1 = fmaxf(acc[i][nc][rr*2 + 1] + s_bias[ch + 1], 0.f);
                float2 st = make_float2(__uint_as_float(tf32r(v0)),
                                        __uint_as_float(tf32r(v1)));
                *(float2*)(g_af + lin*64 + ch) = st;
            }
        }
    }
}

// ---------------------------------------------------------------------------
// conv2: tf32 single-pass 64->64 (gamma|beta) + InstanceNorm.
// 512 thr (8m x 2n), occ 1. A single (620 rows x 272B), B dbuf 16KB.
// ---------------------------------------------------------------------------
#define ASTG2 (AROWS * ASTRIDE2)
#define C2_DSMEM (ASTG2 + 2*16384)
__global__ __launch_bounds__(512, 1)
void conv2_kernel(const float* __restrict__ x,
                  const float* __restrict__ bg, const float* __restrict__ bb_,
                  const int* __restrict__ ycls, float* __restrict__ out) {
    extern __shared__ char dsm[];
    __shared__ float s_mu[32], s_rs[32], s_bg[32], s_bb[32];

    int tile = blockIdx.x, pz = blockIdx.y + 1, b = blockIdx.z;
    int cls = ycls[b];
    int tid = threadIdx.x, wid = tid >> 5, lane = tid & 31;
    u32 base = (smem_u32(dsm) + 127) & ~127u;
    if (tid < 32) {
        s_mu[tid] = g_mu[b*32 + tid];
        s_rs[tid] = g_rsig[b*32 + tid];
        s_bg[tid] = bg[cls*32 + tid];
        s_bb[tid] = bb_[cls*32 + tid];
    }
    __syncthreads();

    int q0 = tile * MT;
    size_t brow = (size_t)XOFF + (size_t)b*PDDD + (size_t)pz*PDD + q0;
    u32 AH = base;

    auto copyA = [&](int kd) {
        size_t blk = brow + (size_t)(kd - 1) * PDD - 51;
        for (int i = tid; i < AROWS * 16; i += 512) {
            int r = i >> 4, j = i & 15;
            cp16f(AH + (u32)r*ASTRIDE2 + (u32)j*16,
                  (const char*)(g_af + (blk + r) * 64) + j*16);
        }
    };
    auto copyB = [&](int t, int s) {
        u32 Bs = base + ASTG2 + (u32)s * 16384;
        const char* bsrc = (const char*)(g_w2f + (size_t)(cls*27 + t) * 4096);
        for (int i = tid; i < 1024; i += 512) cp16f(Bs + i*16, bsrc + i*16);
    };

    float acc[4][4][4];
    #pragma unroll
    for (int i = 0; i < 4; i++)
        #pragma unroll
        for (int j = 0; j < 4; j++)
            #pragma unroll
            for (int q = 0; q < 4; q++) acc[i][j][q] = 0.f;

    int arow = (wid >> 1) * 64;
    int nslot = wid & 1;
    int lr4 = lane >> 2, lc4 = lane & 3;

    copyA(0); copyB(0, 0); cp_commit();
    for (int t = 0; t < 27; t++) {
        int kd = t / 9, kh = (t % 9) / 3, kw = t % 3;
        cp_wait0();
        __syncthreads();
        int nt = t + 1;
        if (nt < 27 && nt % 9 != 0) { copyB(nt, nt & 1); cp_commit(); }
        u32 Bs = base + ASTG2 + (u32)(t & 1) * 16384;
        int rowoff = kh * 50 + kw;
        u32 abase[4];
        #pragma unroll
        for (int i = 0; i < 4; i++)
            abase[i] = AH + (u32)(arow + 16*i + lr4 + rowoff) * ASTRIDE2 + (u32)lc4 * 4;
        #pragma unroll
        for (int ks = 0; ks < 8; ks++) {
            u32 a[4][4];
            #pragma unroll
            for (int i = 0; i < 4; i++) {
                lds32(a[i][0], abase[i] + ks*32);
                lds32(a[i][1], abase[i] + 8*ASTRIDE2 + ks*32);
                lds32(a[i][2], abase[i] + ks*32 + 16);
                lds32(a[i][3], abase[i] + 8*ASTRIDE2 + ks*32 + 16);
            }
            u32 bf[4][2];
            #pragma unroll
            for (int nc = 0; nc < 4; nc++)
                lds64(bf[nc][0], bf[nc][1],
                      Bs + (u32)(((ks*8 + nslot*4 + nc)*32 + lane)*8));
            #pragma unroll
            for (int i = 0; i < 4; i++)
                #pragma unroll
                for (int nc = 0; nc < 4; nc++)
                    mmatf32(acc[i][nc], a[i], bf[nc][0], bf[nc][1]);
        }
        if (nt < 27 && nt % 9 == 0) {
            __syncthreads();
            copyA(nt / 9); copyB(nt, nt & 1); cp_commit();
        }
    }

    // ---------- exchange epilogue ----------
    __syncthreads();
    float* sg = (float*)(dsm + (base - smem_u32(dsm)));
    float* sb = sg + 512 * 33;

    int qr = lane >> 2, qc = (lane & 3) * 2;
    #pragma unroll
    for (int i = 0; i < 4; i++) {
        #pragma unroll
        for (int rr = 0; rr < 2; rr++) {
            int m = arow + 16*i + 8*rr + qr;
            #pragma unroll
            for (int nc = 0; nc < 4; nc++) {
                int n = nslot*32 + nc*8 + qc;
                float v0 = acc[i][nc][rr*2 + 0];
                float v1 = acc[i][nc][rr*2 + 1];
                if (n < 32) { sg[m*33 + n] = v0; sg[m*33 + n + 1] = v1; }
                else        { sb[m*33 + n - 32] = v0; sb[m*33 + n - 31] = v1; }
            }
        }
    }
    __syncthreads();

    if (tid < MT) {
        int q = q0 + tid;
        int py = q / 50, px = q - py * 50;
        if (py >= 1 && py <= 48 && px >= 1 && px <= 48) {
            size_t sidx = (size_t)b*32*VNNN + (size_t)(pz-1)*VNN + (py-1)*VN + (px-1);
            #pragma unroll 8
            for (int ch = 0; ch < 32; ch++) {
                float gm = sg[tid*33 + ch] + s_bg[ch];
                float bt = sb[tid*33 + ch] + s_bb[ch];
                float xv = x[sidx + (size_t)ch * VNNN];
                out[sidx + (size_t)ch * VNNN] =
                    (xv - s_mu[ch]) * s_rs[ch] * (1.f + gm) + bt;
            }
        }
    }
}

// ---------------------------------------------------------------------------
extern "C" void kernel_launch(void* const* d_in, const int* in_sizes, int n_in,
                              void* d_out, int out_size) {
    const float* x       = (const float*)d_in[0];
    const int*   y       = (const int*)d_in[1];
    const float* Wshared = (const float*)d_in[2];
    const float* bshared = (const float*)d_in[3];
    const float* Wgamma  = (const float*)d_in[4];
    const float* bgamma  = (const float*)d_in[5];
    const float* Wbeta   = (const float*)d_in[6];
    const float* bbeta   = (const float*)d_in[7];
    float* out = (float*)d_out;

    cudaFuncSetAttribute(conv1_kernel, cudaFuncAttributeMaxDynamicSharedMemorySize, C1_DSMEM);
    cudaFuncSetAttribute(conv2_kernel, cudaFuncAttributeMaxDynamicSharedMemorySize, C2_DSMEM);

    stats_kernel<<<NB * 32, 256>>>(x);
    xpose_kernel<<<dim3(PD, NB), 256>>>(x);
    zhalo_kernel<<<dim3(PD, NB), 256>>>();
    prepb1_kernel<<<dim3(27, 4), 256>>>(Wshared);
    prepb2_kernel<<<dim3(27, 4), 256>>>(Wgamma, Wbeta);

    conv1_kernel<<<dim3(NTILE, 48, NB), 512, C1_DSMEM>>>(y, bshared);
    conv2_kernel<<<dim3(NTILE, 48, NB), 512, C2_DSMEM>>>(x, bgamma, bbeta, y, out);
}